// round 2
// baseline (speedup 1.0000x reference)
#include <cuda_runtime.h>
#include <math.h>

#define N_NODES 30000
#define N_REL   38
#define N_EDGE  200000
#define HID     64

// ---------------- scratch (static __device__ — no allocation allowed) ----------------
__device__ float g_H  [(size_t)N_REL * N_NODES * HID];   // 291.84 MB
__device__ float g_OUT[(size_t)N_REL * N_NODES * HID];   // 291.84 MB
__device__ float g_Ssrc[N_REL * N_NODES];
__device__ float g_Sdst[N_REL * N_NODES];
__device__ float g_DEN [N_REL * N_NODES];

__device__ __forceinline__ float lrelu(float x) { return x > 0.f ? x : 0.2f * x; }

// ---------------- zero OUT + DEN ----------------
__global__ void zero_kernel() {
    size_t i = (size_t)blockIdx.x * blockDim.x + threadIdx.x;
    size_t tot4 = (size_t)N_REL * N_NODES * HID / 4;     // 18.24M float4
    if (i < tot4) ((float4*)g_OUT)[i] = make_float4(0.f, 0.f, 0.f, 0.f);
    if (i < (size_t)N_REL * N_NODES) g_DEN[i] = 0.f;
}

// ---------------- per-relation GEMM H = emb @ W[r], fused s_src/s_dst ----------------
// block: 256 threads, tile 32 nodes x 64 hid. thread t: row = t>>3, cols (t&7)*8..+7
__global__ __launch_bounds__(256) void gemm_s_kernel(
    const float* __restrict__ emb, const float* __restrict__ W,
    const float* __restrict__ att_src, const float* __restrict__ att_dst)
{
    __shared__ __align__(16) float sW[64 * 64];
    __shared__ float sE[32 * 65];
    __shared__ float sH[32 * 65];
    __shared__ float sAs[64], sAd[64];

    const int rel = blockIdx.y;
    const int n0  = blockIdx.x * 32;
    const int tid = threadIdx.x;

    const float* Wr = W + rel * 64 * 64;
    for (int i = tid; i < 4096; i += 256) sW[i] = Wr[i];
    if (tid < 64) { sAs[tid] = att_src[rel * 64 + tid]; sAd[tid] = att_dst[rel * 64 + tid]; }
    for (int i = tid; i < 2048; i += 256) {
        int row = i >> 6, k = i & 63;
        int n = n0 + row;
        sE[row * 65 + k] = (n < N_NODES) ? emb[(size_t)n * 64 + k] : 0.f;
    }
    __syncthreads();

    const int row = tid >> 3;
    const int kb  = (tid & 7) * 8;
    float acc[8];
#pragma unroll
    for (int q = 0; q < 8; q++) acc[q] = 0.f;

#pragma unroll 8
    for (int j = 0; j < 64; ++j) {
        float ev = sE[row * 65 + j];
        const float4* wv = (const float4*)&sW[j * 64 + kb];
        float4 w0 = wv[0], w1 = wv[1];
        acc[0] += ev * w0.x; acc[1] += ev * w0.y; acc[2] += ev * w0.z; acc[3] += ev * w0.w;
        acc[4] += ev * w1.x; acc[5] += ev * w1.y; acc[6] += ev * w1.z; acc[7] += ev * w1.w;
    }

    int n = n0 + row;
    if (n < N_NODES) {
        float* hp = &g_H[((size_t)rel * N_NODES + n) * 64 + kb];
        ((float4*)hp)[0] = make_float4(acc[0], acc[1], acc[2], acc[3]);
        ((float4*)hp)[1] = make_float4(acc[4], acc[5], acc[6], acc[7]);
    }
#pragma unroll
    for (int q = 0; q < 8; q++) sH[row * 65 + kb + q] = acc[q];
    __syncthreads();

    if (tid < 32) {
        int nn = n0 + tid;
        if (nn < N_NODES) {
            float s1 = 0.f, s2 = 0.f;
#pragma unroll 8
            for (int k = 0; k < 64; ++k) {
                float h = sH[tid * 65 + k];
                s1 += h * sAs[k];
                s2 += h * sAd[k];
            }
            g_Ssrc[rel * N_NODES + nn] = s1;
            g_Sdst[rel * N_NODES + nn] = s2;
        }
    }
}

// ---------------- edge pass A: den[dst] += exp(lrelu(s_src[src]+s_dst[dst])) ----------------
// covers E real edges + N self loops per relation
__global__ __launch_bounds__(256) void edge_pass_a(const int* __restrict__ edges) {
    const int rel = blockIdx.y;
    const int idx = blockIdx.x * 256 + threadIdx.x;
    int s, d;
    if (idx < N_EDGE) {
        s = __ldg(&edges[(size_t)rel * 2 * N_EDGE + idx]);
        d = __ldg(&edges[(size_t)rel * 2 * N_EDGE + N_EDGE + idx]);
    } else if (idx < N_EDGE + N_NODES) {
        s = d = idx - N_EDGE;
    } else return;
    float e = lrelu(__ldg(&g_Ssrc[rel * N_NODES + s]) + __ldg(&g_Sdst[rel * N_NODES + d]));
    atomicAdd(&g_DEN[rel * N_NODES + d], __expf(e));
}

// ---------------- edge pass B (per relation for L2 locality): OUT[dst] += alpha*H[src] ----------------
// 16 lanes per edge, float4 red per lane
__global__ __launch_bounds__(256) void scatter_kernel(const int* __restrict__ edges, int rel) {
    const int t    = blockIdx.x * 256 + threadIdx.x;
    const int edge = t >> 4;
    const int sub  = threadIdx.x & 15;
    if (edge >= N_EDGE) return;
    const int* eb = edges + (size_t)rel * 2 * N_EDGE;
    const int s = __ldg(&eb[edge]);
    const int d = __ldg(&eb[N_EDGE + edge]);
    const float* ss = g_Ssrc + rel * N_NODES;
    const float* sd = g_Sdst + rel * N_NODES;
    const float* dn = g_DEN  + rel * N_NODES;
    float e = lrelu(__ldg(&ss[s]) + __ldg(&sd[d]));
    float alpha = __expf(e) / __ldg(&dn[d]);
    const size_t hb = ((size_t)rel * N_NODES + s) * 64 + sub * 4;
    const size_t ob = ((size_t)rel * N_NODES + d) * 64 + sub * 4;
    float4 hv = *(const float4*)&g_H[hb];
    float* op = &g_OUT[ob];
    asm volatile("red.global.add.v4.f32 [%0], {%1,%2,%3,%4};"
                 :: "l"(op), "f"(alpha * hv.x), "f"(alpha * hv.y),
                    "f"(alpha * hv.z), "f"(alpha * hv.w)
                 : "memory");
}

// ---------------- final: fused self-loop + bias + 2-layer MLP ----------------
// block: 128 threads, tile 32 nodes x 64 out. thread: rows rp, rp+16; cols cg*8..+7
__global__ __launch_bounds__(128) void final_kernel(
    const float* __restrict__ emb, const float* __restrict__ bias,
    const float* __restrict__ W1, const float* __restrict__ b1,
    const float* __restrict__ W2, const float* __restrict__ b2,
    const int* __restrict__ nodes, float* __restrict__ out)
{
    __shared__ float sA[32 * 65];
    __shared__ __align__(16) float sB[64 * 64];
    __shared__ float sAlpha[32];
    __shared__ int   sNd[32];

    const int n0  = blockIdx.x * 32;
    const int tid = threadIdx.x;
    const int rp  = tid >> 3;          // 0..15  (rows rp and rp+16)
    const int cg  = tid & 7;           // cols cg*8 .. cg*8+7

    if (tid < 32) {
        int nn = n0 + tid;
        sNd[tid] = (nn < N_NODES) ? nodes[nn] : -1;
    }

    float acc0[8], acc1[8];
#pragma unroll
    for (int q = 0; q < 8; q++) { acc0[q] = 0.f; acc1[q] = 0.f; }

    for (int seg = 0; seg < N_REL + 1; ++seg) {
        __syncthreads();   // previous compute done with sA/sB
        const float* w1c = W1 + (size_t)seg * 64 * 64;
        for (int i = tid; i < 4096; i += 128) sB[i] = w1c[i];
        if (seg > 0 && tid < 32) {
            int nd = sNd[tid];
            float a = 0.f;
            if (nd >= 0) {
                int base = (seg - 1) * N_NODES + nd;
                float e = lrelu(g_Ssrc[base] + g_Sdst[base]);
                a = __expf(e) / g_DEN[base];
            }
            sAlpha[tid] = a;
        }
        __syncthreads();

        // build A tile: 512 float4s
        if (seg == 0) {
            for (int i = tid; i < 512; i += 128) {
                int row = i >> 4, k = (i & 15) * 4;
                int nd = sNd[row];
                float4 v = make_float4(0.f, 0.f, 0.f, 0.f);
                if (nd >= 0) v = *(const float4*)&emb[(size_t)nd * 64 + k];
                sA[row * 65 + k] = v.x; sA[row * 65 + k + 1] = v.y;
                sA[row * 65 + k + 2] = v.z; sA[row * 65 + k + 3] = v.w;
            }
        } else {
            const int r = seg - 1;
            for (int i = tid; i < 512; i += 128) {
                int row = i >> 4, k = (i & 15) * 4;
                int nd = sNd[row];
                float4 v = make_float4(0.f, 0.f, 0.f, 0.f);
                if (nd >= 0) {
                    size_t base64 = ((size_t)r * N_NODES + nd) * 64 + k;
                    float4 o = *(const float4*)&g_OUT[base64];
                    float4 h = *(const float4*)&g_H[base64];
                    float4 bvec = *(const float4*)&bias[r * 64 + k];
                    float a = sAlpha[row];
                    v.x = o.x + a * h.x + bvec.x;
                    v.y = o.y + a * h.y + bvec.y;
                    v.z = o.z + a * h.z + bvec.z;
                    v.w = o.w + a * h.w + bvec.w;
                }
                sA[row * 65 + k] = v.x; sA[row * 65 + k + 1] = v.y;
                sA[row * 65 + k + 2] = v.z; sA[row * 65 + k + 3] = v.w;
            }
        }
        __syncthreads();

#pragma unroll 4
        for (int k = 0; k < 64; ++k) {
            float a0 = sA[rp * 65 + k];
            float a1 = sA[(rp + 16) * 65 + k];
            const float4* bp = (const float4*)&sB[k * 64 + cg * 8];
            float4 b0 = bp[0], b1v = bp[1];
            acc0[0] += a0 * b0.x;  acc0[1] += a0 * b0.y;  acc0[2] += a0 * b0.z;  acc0[3] += a0 * b0.w;
            acc0[4] += a0 * b1v.x; acc0[5] += a0 * b1v.y; acc0[6] += a0 * b1v.z; acc0[7] += a0 * b1v.w;
            acc1[0] += a1 * b0.x;  acc1[1] += a1 * b0.y;  acc1[2] += a1 * b0.z;  acc1[3] += a1 * b0.w;
            acc1[4] += a1 * b1v.x; acc1[5] += a1 * b1v.y; acc1[6] += a1 * b1v.z; acc1[7] += a1 * b1v.w;
        }
    }

    // h1 = tanh(acc + b1) -> sA; load W2 -> sB
    __syncthreads();
#pragma unroll
    for (int q = 0; q < 8; q++) {
        float bb = b1[cg * 8 + q];
        sA[rp * 65 + cg * 8 + q]        = tanhf(acc0[q] + bb);
        sA[(rp + 16) * 65 + cg * 8 + q] = tanhf(acc1[q] + bb);
    }
    for (int i = tid; i < 4096; i += 128) sB[i] = W2[i];
    __syncthreads();

    float o0[8], o1[8];
#pragma unroll
    for (int q = 0; q < 8; q++) { o0[q] = 0.f; o1[q] = 0.f; }
#pragma unroll 4
    for (int k = 0; k < 64; ++k) {
        float a0 = sA[rp * 65 + k];
        float a1 = sA[(rp + 16) * 65 + k];
        const float4* bp = (const float4*)&sB[k * 64 + cg * 8];
        float4 b0 = bp[0], b1v = bp[1];
        o0[0] += a0 * b0.x;  o0[1] += a0 * b0.y;  o0[2] += a0 * b0.z;  o0[3] += a0 * b0.w;
        o0[4] += a0 * b1v.x; o0[5] += a0 * b1v.y; o0[6] += a0 * b1v.z; o0[7] += a0 * b1v.w;
        o1[0] += a1 * b0.x;  o1[1] += a1 * b0.y;  o1[2] += a1 * b0.z;  o1[3] += a1 * b0.w;
        o1[4] += a1 * b1v.x; o1[5] += a1 * b1v.y; o1[6] += a1 * b1v.z; o1[7] += a1 * b1v.w;
    }

    int nn0 = n0 + rp, nn1 = n0 + rp + 16;
    if (nn0 < N_NODES) {
        float4 v0 = make_float4(o0[0] + b2[cg*8+0], o0[1] + b2[cg*8+1], o0[2] + b2[cg*8+2], o0[3] + b2[cg*8+3]);
        float4 v1 = make_float4(o0[4] + b2[cg*8+4], o0[5] + b2[cg*8+5], o0[6] + b2[cg*8+6], o0[7] + b2[cg*8+7]);
        ((float4*)&out[(size_t)nn0 * 64 + cg * 8])[0] = v0;
        ((float4*)&out[(size_t)nn0 * 64 + cg * 8])[1] = v1;
    }
    if (nn1 < N_NODES) {
        float4 v0 = make_float4(o1[0] + b2[cg*8+0], o1[1] + b2[cg*8+1], o1[2] + b2[cg*8+2], o1[3] + b2[cg*8+3]);
        float4 v1 = make_float4(o1[4] + b2[cg*8+4], o1[5] + b2[cg*8+5], o1[6] + b2[cg*8+6], o1[7] + b2[cg*8+7]);
        ((float4*)&out[(size_t)nn1 * 64 + cg * 8])[0] = v0;
        ((float4*)&out[(size_t)nn1 * 64 + cg * 8])[1] = v1;
    }
}

// ---------------- launch ----------------
extern "C" void kernel_launch(void* const* d_in, const int* in_sizes, int n_in,
                              void* d_out, int out_size) {
    const float* emb     = (const float*)d_in[0];
    const float* W       = (const float*)d_in[1];
    const float* att_src = (const float*)d_in[2];
    const float* att_dst = (const float*)d_in[3];
    const float* bias    = (const float*)d_in[4];
    const float* W1      = (const float*)d_in[5];
    const float* b1      = (const float*)d_in[6];
    const float* W2      = (const float*)d_in[7];
    const float* b2      = (const float*)d_in[8];
    const int*   edges   = (const int*)d_in[9];
    const int*   nodes   = (const int*)d_in[10];
    float*       out     = (float*)d_out;

    const size_t tot4 = (size_t)N_REL * N_NODES * HID / 4;
    zero_kernel<<<(unsigned)((tot4 + 255) / 256), 256>>>();

    dim3 g1((N_NODES + 31) / 32, N_REL);
    gemm_s_kernel<<<g1, 256>>>(emb, W, att_src, att_dst);

    dim3 g2((N_EDGE + N_NODES + 255) / 256, N_REL);
    edge_pass_a<<<g2, 256>>>(edges);

    const int sblocks = (N_EDGE * 16 + 255) / 256;   // 12500
    for (int r = 0; r < N_REL; ++r)
        scatter_kernel<<<sblocks, 256>>>(edges, r);

    final_kernel<<<(N_NODES + 31) / 32, 128>>>(emb, bias, W1, b1, W2, b2, nodes, out);
}

// round 3
// speedup vs baseline: 1.1940x; 1.1940x over previous
#include <cuda_runtime.h>
#include <math.h>

#define N_NODES 30000
#define N_REL   38
#define N_EDGE  200000
#define HID     64
#define E_TOT   (N_EDGE + N_NODES)   // real edges + self loops

// ---------------- scratch (static __device__ — no allocation allowed) ----------------
__device__ float g_H  [(size_t)N_REL * N_NODES * HID];   // 291.84 MB
__device__ float g_OUT[(size_t)N_REL * N_NODES * HID];   // 291.84 MB (unnormalized Σ w·h)
__device__ float g_Ssrc[N_REL * N_NODES];
__device__ float g_Sdst[N_REL * N_NODES];
__device__ float g_DEN [N_REL * N_NODES];                // Σ w (incl. self loop)

__device__ __forceinline__ float lrelu(float x) { return x > 0.f ? x : 0.2f * x; }

// ---------------- zero OUT + DEN ----------------
__global__ void zero_kernel() {
    size_t i = (size_t)blockIdx.x * blockDim.x + threadIdx.x;
    size_t tot4 = (size_t)N_REL * N_NODES * HID / 4;
    if (i < tot4) ((float4*)g_OUT)[i] = make_float4(0.f, 0.f, 0.f, 0.f);
    if (i < (size_t)N_REL * N_NODES) g_DEN[i] = 0.f;
}

// ---------------- per-relation GEMM H = emb @ W[r], fused s_src/s_dst ----------------
// 256 threads, 64-node x 64-hid tile, 2 rows per thread (register blocked)
__global__ __launch_bounds__(256) void gemm_s_kernel(
    const float* __restrict__ emb, const float* __restrict__ W,
    const float* __restrict__ att_src, const float* __restrict__ att_dst)
{
    __shared__ __align__(16) float sW[64 * 64];
    __shared__ float sE[64 * 65];

    const int rel = blockIdx.y;
    const int n0  = blockIdx.x * 64;
    const int tid = threadIdx.x;

    const float* Wr = W + rel * 4096;
    for (int i = tid; i < 4096; i += 256) sW[i] = Wr[i];
    for (int i = tid; i < 4096; i += 256) {
        int row = i >> 6, k = i & 63;
        int n = n0 + row;
        sE[row * 65 + k] = (n < N_NODES) ? emb[(size_t)n * 64 + k] : 0.f;
    }

    const int kb = (tid & 7) * 8;
    float as[8], ad[8];
#pragma unroll
    for (int q = 0; q < 8; q++) {
        as[q] = att_src[rel * 64 + kb + q];
        ad[q] = att_dst[rel * 64 + kb + q];
    }
    __syncthreads();

    const int r0 = tid >> 3;          // 0..31 ; rows r0 and r0+32
    float acc0[8], acc1[8];
#pragma unroll
    for (int q = 0; q < 8; q++) { acc0[q] = 0.f; acc1[q] = 0.f; }

#pragma unroll 8
    for (int j = 0; j < 64; ++j) {
        float e0 = sE[r0 * 65 + j];
        float e1 = sE[(r0 + 32) * 65 + j];
        const float4* wv = (const float4*)&sW[j * 64 + kb];
        float4 w0 = wv[0], w1 = wv[1];
        acc0[0] += e0 * w0.x; acc0[1] += e0 * w0.y; acc0[2] += e0 * w0.z; acc0[3] += e0 * w0.w;
        acc0[4] += e0 * w1.x; acc0[5] += e0 * w1.y; acc0[6] += e0 * w1.z; acc0[7] += e0 * w1.w;
        acc1[0] += e1 * w0.x; acc1[1] += e1 * w0.y; acc1[2] += e1 * w0.z; acc1[3] += e1 * w0.w;
        acc1[4] += e1 * w1.x; acc1[5] += e1 * w1.y; acc1[6] += e1 * w1.z; acc1[7] += e1 * w1.w;
    }

    const int n_0 = n0 + r0, n_1 = n0 + r0 + 32;
    if (n_0 < N_NODES) {
        float* hp = &g_H[((size_t)rel * N_NODES + n_0) * 64 + kb];
        ((float4*)hp)[0] = make_float4(acc0[0], acc0[1], acc0[2], acc0[3]);
        ((float4*)hp)[1] = make_float4(acc0[4], acc0[5], acc0[6], acc0[7]);
    }
    if (n_1 < N_NODES) {
        float* hp = &g_H[((size_t)rel * N_NODES + n_1) * 64 + kb];
        ((float4*)hp)[0] = make_float4(acc1[0], acc1[1], acc1[2], acc1[3]);
        ((float4*)hp)[1] = make_float4(acc1[4], acc1[5], acc1[6], acc1[7]);
    }

    // s_src/s_dst via 8-lane butterfly reduce (lanes with same row are cg=0..7)
    float p0s = 0.f, p0d = 0.f, p1s = 0.f, p1d = 0.f;
#pragma unroll
    for (int q = 0; q < 8; q++) {
        p0s += acc0[q] * as[q]; p0d += acc0[q] * ad[q];
        p1s += acc1[q] * as[q]; p1d += acc1[q] * ad[q];
    }
#pragma unroll
    for (int off = 1; off < 8; off <<= 1) {
        p0s += __shfl_xor_sync(0xffffffffu, p0s, off);
        p0d += __shfl_xor_sync(0xffffffffu, p0d, off);
        p1s += __shfl_xor_sync(0xffffffffu, p1s, off);
        p1d += __shfl_xor_sync(0xffffffffu, p1d, off);
    }
    if ((tid & 7) == 0) {
        if (n_0 < N_NODES) {
            g_Ssrc[rel * N_NODES + n_0] = p0s;
            g_Sdst[rel * N_NODES + n_0] = p0d;
        }
        if (n_1 < N_NODES) {
            g_Ssrc[rel * N_NODES + n_1] = p1s;
            g_Sdst[rel * N_NODES + n_1] = p1d;
        }
    }
}

// ---------------- scatter (per relation-pair): OUT[dst] += w*H[src], DEN[dst] += w ----------------
// 16 lanes per edge; covers E real edges + N self loops. Lane sub==0 computes w, shfl-broadcast.
// Grid.x sized so thread count is exact: E_TOT*16 = 3,680,000 = 14375 * 256 (no partial warps).
__global__ __launch_bounds__(256) void scatter_kernel(const int* __restrict__ edges, int rel0) {
    const int rel  = rel0 + blockIdx.y;
    const int t    = blockIdx.x * 256 + threadIdx.x;
    const int edge = t >> 4;
    const int sub  = threadIdx.x & 15;
    const int lane = threadIdx.x & 31;

    const int*   eb = edges + (size_t)rel * 2 * N_EDGE;
    const float* ss = g_Ssrc + rel * N_NODES;
    const float* sd = g_Sdst + rel * N_NODES;

    int s = 0, d = 0;
    float w = 0.f;
    if (sub == 0) {
        if (edge < N_EDGE) {
            s = __ldg(&eb[edge]);
            d = __ldg(&eb[N_EDGE + edge]);
        } else {
            s = d = edge - N_EDGE;      // self loop
        }
        float e = lrelu(__ldg(&ss[s]) + __ldg(&sd[d]));
        w = __expf(e);
        atomicAdd(&g_DEN[rel * N_NODES + d], w);
    }
    const int srcLane = lane & 16;
    s = __shfl_sync(0xffffffffu, s, srcLane);
    d = __shfl_sync(0xffffffffu, d, srcLane);
    w = __shfl_sync(0xffffffffu, w, srcLane);

    const size_t hb = ((size_t)rel * N_NODES + s) * 64 + sub * 4;
    const size_t ob = ((size_t)rel * N_NODES + d) * 64 + sub * 4;
    float4 hv = *(const float4*)&g_H[hb];
    float* op = &g_OUT[ob];
    asm volatile("red.global.add.v4.f32 [%0], {%1,%2,%3,%4};"
                 :: "l"(op), "f"(w * hv.x), "f"(w * hv.y),
                    "f"(w * hv.z), "f"(w * hv.w)
                 : "memory");
}

// ---------------- final: normalize + bias + 2-layer MLP ----------------
// 256 threads, 64-node tile, 2 rows per thread. A[seg] = OUT/den + bias (seg>0), emb (seg 0).
__global__ __launch_bounds__(256) void final_kernel(
    const float* __restrict__ emb, const float* __restrict__ bias,
    const float* __restrict__ W1, const float* __restrict__ b1,
    const float* __restrict__ W2, const float* __restrict__ b2,
    const int* __restrict__ nodes, float* __restrict__ out)
{
    __shared__ float sA[64 * 65];
    __shared__ __align__(16) float sB[64 * 64];
    __shared__ float sInv[64];
    __shared__ int   sNd[64];

    const int n0  = blockIdx.x * 64;
    const int tid = threadIdx.x;
    const int rp  = tid >> 3;          // 0..31 ; rows rp and rp+32
    const int cg  = tid & 7;

    if (tid < 64) {
        int nn = n0 + tid;
        sNd[tid] = (nn < N_NODES) ? nodes[nn] : -1;
    }

    float acc0[8], acc1[8];
#pragma unroll
    for (int q = 0; q < 8; q++) { acc0[q] = 0.f; acc1[q] = 0.f; }

    for (int seg = 0; seg < N_REL + 1; ++seg) {
        __syncthreads();   // prior compute done with sA/sB
        const float* w1c = W1 + (size_t)seg * 64 * 64;
        for (int i = tid; i < 4096; i += 256) sB[i] = w1c[i];
        if (seg > 0 && tid < 64) {
            int nd = sNd[tid];
            sInv[tid] = (nd >= 0) ? (1.f / g_DEN[(seg - 1) * N_NODES + nd]) : 0.f;
        }
        __syncthreads();

        // build A tile: 1024 float4s (4 per thread)
        if (seg == 0) {
            for (int i = tid; i < 1024; i += 256) {
                int row = i >> 4, k = (i & 15) * 4;
                int nd = sNd[row];
                float4 v = make_float4(0.f, 0.f, 0.f, 0.f);
                if (nd >= 0) v = *(const float4*)&emb[(size_t)nd * 64 + k];
                sA[row * 65 + k]     = v.x; sA[row * 65 + k + 1] = v.y;
                sA[row * 65 + k + 2] = v.z; sA[row * 65 + k + 3] = v.w;
            }
        } else {
            const int r = seg - 1;
            for (int i = tid; i < 1024; i += 256) {
                int row = i >> 4, k = (i & 15) * 4;
                int nd = sNd[row];
                float4 v = make_float4(0.f, 0.f, 0.f, 0.f);
                if (nd >= 0) {
                    float4 o    = *(const float4*)&g_OUT[((size_t)r * N_NODES + nd) * 64 + k];
                    float4 bvec = *(const float4*)&bias[r * 64 + k];
                    float inv = sInv[row];
                    v.x = o.x * inv + bvec.x;
                    v.y = o.y * inv + bvec.y;
                    v.z = o.z * inv + bvec.z;
                    v.w = o.w * inv + bvec.w;
                }
                sA[row * 65 + k]     = v.x; sA[row * 65 + k + 1] = v.y;
                sA[row * 65 + k + 2] = v.z; sA[row * 65 + k + 3] = v.w;
            }
        }
        __syncthreads();

#pragma unroll 8
        for (int k = 0; k < 64; ++k) {
            float a0 = sA[rp * 65 + k];
            float a1 = sA[(rp + 32) * 65 + k];
            const float4* bp = (const float4*)&sB[k * 64 + cg * 8];
            float4 b0 = bp[0], b1v = bp[1];
            acc0[0] += a0 * b0.x;  acc0[1] += a0 * b0.y;  acc0[2] += a0 * b0.z;  acc0[3] += a0 * b0.w;
            acc0[4] += a0 * b1v.x; acc0[5] += a0 * b1v.y; acc0[6] += a0 * b1v.z; acc0[7] += a0 * b1v.w;
            acc1[0] += a1 * b0.x;  acc1[1] += a1 * b0.y;  acc1[2] += a1 * b0.z;  acc1[3] += a1 * b0.w;
            acc1[4] += a1 * b1v.x; acc1[5] += a1 * b1v.y; acc1[6] += a1 * b1v.z; acc1[7] += a1 * b1v.w;
        }
    }

    // h1 = tanh(acc + b1) -> sA ; W2 -> sB
    __syncthreads();
#pragma unroll
    for (int q = 0; q < 8; q++) {
        float bb = b1[cg * 8 + q];
        sA[rp * 65 + cg * 8 + q]        = tanhf(acc0[q] + bb);
        sA[(rp + 32) * 65 + cg * 8 + q] = tanhf(acc1[q] + bb);
    }
    for (int i = tid; i < 4096; i += 256) sB[i] = W2[i];
    __syncthreads();

    float o0[8], o1[8];
#pragma unroll
    for (int q = 0; q < 8; q++) { o0[q] = 0.f; o1[q] = 0.f; }
#pragma unroll 8
    for (int k = 0; k < 64; ++k) {
        float a0 = sA[rp * 65 + k];
        float a1 = sA[(rp + 32) * 65 + k];
        const float4* bp = (const float4*)&sB[k * 64 + cg * 8];
        float4 b0 = bp[0], b1v = bp[1];
        o0[0] += a0 * b0.x;  o0[1] += a0 * b0.y;  o0[2] += a0 * b0.z;  o0[3] += a0 * b0.w;
        o0[4] += a0 * b1v.x; o0[5] += a0 * b1v.y; o0[6] += a0 * b1v.z; o0[7] += a0 * b1v.w;
        o1[0] += a1 * b0.x;  o1[1] += a1 * b0.y;  o1[2] += a1 * b0.z;  o1[3] += a1 * b0.w;
        o1[4] += a1 * b1v.x; o1[5] += a1 * b1v.y; o1[6] += a1 * b1v.z; o1[7] += a1 * b1v.w;
    }

    int nn0 = n0 + rp, nn1 = n0 + rp + 32;
    if (nn0 < N_NODES) {
        float4 v0 = make_float4(o0[0] + b2[cg*8+0], o0[1] + b2[cg*8+1], o0[2] + b2[cg*8+2], o0[3] + b2[cg*8+3]);
        float4 v1 = make_float4(o0[4] + b2[cg*8+4], o0[5] + b2[cg*8+5], o0[6] + b2[cg*8+6], o0[7] + b2[cg*8+7]);
        ((float4*)&out[(size_t)nn0 * 64 + cg * 8])[0] = v0;
        ((float4*)&out[(size_t)nn0 * 64 + cg * 8])[1] = v1;
    }
    if (nn1 < N_NODES) {
        float4 v0 = make_float4(o1[0] + b2[cg*8+0], o1[1] + b2[cg*8+1], o1[2] + b2[cg*8+2], o1[3] + b2[cg*8+3]);
        float4 v1 = make_float4(o1[4] + b2[cg*8+4], o1[5] + b2[cg*8+5], o1[6] + b2[cg*8+6], o1[7] + b2[cg*8+7]);
        ((float4*)&out[(size_t)nn1 * 64 + cg * 8])[0] = v0;
        ((float4*)&out[(size_t)nn1 * 64 + cg * 8])[1] = v1;
    }
}

// ---------------- launch ----------------
extern "C" void kernel_launch(void* const* d_in, const int* in_sizes, int n_in,
                              void* d_out, int out_size) {
    const float* emb     = (const float*)d_in[0];
    const float* W       = (const float*)d_in[1];
    const float* att_src = (const float*)d_in[2];
    const float* att_dst = (const float*)d_in[3];
    const float* bias    = (const float*)d_in[4];
    const float* W1      = (const float*)d_in[5];
    const float* b1      = (const float*)d_in[6];
    const float* W2      = (const float*)d_in[7];
    const float* b2      = (const float*)d_in[8];
    const int*   edges   = (const int*)d_in[9];
    const int*   nodes   = (const int*)d_in[10];
    float*       out     = (float*)d_out;

    const size_t tot4 = (size_t)N_REL * N_NODES * HID / 4;
    zero_kernel<<<(unsigned)((tot4 + 255) / 256), 256>>>();

    dim3 g1((N_NODES + 63) / 64, N_REL);
    gemm_s_kernel<<<g1, 256>>>(emb, W, att_src, att_dst);

    // 16 lanes per (edge|self-loop): E_TOT*16 threads, exact multiple of 256
    const int sblocks = (E_TOT * 16) / 256;   // 14375
    for (int r = 0; r < N_REL; r += 2) {
        dim3 gs(sblocks, 2);
        scatter_kernel<<<gs, 256>>>(edges, r);
    }

    final_kernel<<<(N_NODES + 63) / 64, 256>>>(emb, bias, W1, b1, W2, b2, nodes, out);
}

// round 4
// speedup vs baseline: 1.4879x; 1.2462x over previous
#include <cuda_runtime.h>
#include <math.h>

#define N_NODES 30000
#define N_REL   38
#define N_EDGE  200000
#define HID     64
#define E_TOT   (N_EDGE + N_NODES)   // real edges + self loops (230000, %4==0)

// ---------------- scratch (static __device__ — no allocation allowed) ----------------
__device__ float g_H  [(size_t)N_REL * N_NODES * HID];   // 291.84 MB
__device__ float g_OUT[(size_t)N_REL * N_NODES * HID];   // unnormalized Σ w·h
__device__ float g_Ssrc[N_REL * N_NODES];
__device__ float g_Sdst[N_REL * N_NODES];
__device__ float g_DEN [N_REL * N_NODES];                // Σ w (incl. self loop)

__device__ __forceinline__ float lrelu(float x) { return x > 0.f ? x : 0.2f * x; }

// ---------------- zero OUT + DEN ----------------
__global__ void zero_kernel() {
    size_t i = (size_t)blockIdx.x * blockDim.x + threadIdx.x;
    size_t tot4 = (size_t)N_REL * N_NODES * HID / 4;
    if (i < tot4) ((float4*)g_OUT)[i] = make_float4(0.f, 0.f, 0.f, 0.f);
    if (i < (size_t)N_REL * N_NODES) g_DEN[i] = 0.f;
}

// ---------------- per-relation GEMM H = emb @ W[r], fused s_src/s_dst ----------------
// 256 threads, 128-node x 64-hid tile, 4 rows per thread. Dynamic smem: sW[4096] + sE[128*65]
__global__ __launch_bounds__(256) void gemm_s_kernel(
    const float* __restrict__ emb, const float* __restrict__ W,
    const float* __restrict__ att_src, const float* __restrict__ att_dst)
{
    extern __shared__ float smem[];
    float* sW = smem;            // 64*64
    float* sE = smem + 4096;     // 128*65

    const int rel = blockIdx.y;
    const int n0  = blockIdx.x * 128;
    const int tid = threadIdx.x;

    const float* Wr = W + rel * 4096;
    for (int i = tid; i < 1024; i += 256)
        ((float4*)sW)[i] = ((const float4*)Wr)[i];
    for (int i = tid; i < 2048; i += 256) {
        int row = i >> 4, k = (i & 15) * 4;
        int n = n0 + row;
        float4 v = make_float4(0.f, 0.f, 0.f, 0.f);
        if (n < N_NODES) v = *(const float4*)&emb[(size_t)n * 64 + k];
        sE[row * 65 + k]     = v.x; sE[row * 65 + k + 1] = v.y;
        sE[row * 65 + k + 2] = v.z; sE[row * 65 + k + 3] = v.w;
    }

    const int kb = (tid & 7) * 8;
    float as[8], ad[8];
#pragma unroll
    for (int q = 0; q < 8; q++) {
        as[q] = att_src[rel * 64 + kb + q];
        ad[q] = att_dst[rel * 64 + kb + q];
    }
    __syncthreads();

    const int r0 = tid >> 3;          // 0..31 ; rows r0, +32, +64, +96
    float acc[4][8];
#pragma unroll
    for (int m = 0; m < 4; m++)
#pragma unroll
        for (int q = 0; q < 8; q++) acc[m][q] = 0.f;

#pragma unroll 4
    for (int j = 0; j < 64; ++j) {
        float e0 = sE[(r0      ) * 65 + j];
        float e1 = sE[(r0 + 32 ) * 65 + j];
        float e2 = sE[(r0 + 64 ) * 65 + j];
        float e3 = sE[(r0 + 96 ) * 65 + j];
        const float4* wv = (const float4*)&sW[j * 64 + kb];
        float4 w0 = wv[0], w1 = wv[1];
        acc[0][0] += e0*w0.x; acc[0][1] += e0*w0.y; acc[0][2] += e0*w0.z; acc[0][3] += e0*w0.w;
        acc[0][4] += e0*w1.x; acc[0][5] += e0*w1.y; acc[0][6] += e0*w1.z; acc[0][7] += e0*w1.w;
        acc[1][0] += e1*w0.x; acc[1][1] += e1*w0.y; acc[1][2] += e1*w0.z; acc[1][3] += e1*w0.w;
        acc[1][4] += e1*w1.x; acc[1][5] += e1*w1.y; acc[1][6] += e1*w1.z; acc[1][7] += e1*w1.w;
        acc[2][0] += e2*w0.x; acc[2][1] += e2*w0.y; acc[2][2] += e2*w0.z; acc[2][3] += e2*w0.w;
        acc[2][4] += e2*w1.x; acc[2][5] += e2*w1.y; acc[2][6] += e2*w1.z; acc[2][7] += e2*w1.w;
        acc[3][0] += e3*w0.x; acc[3][1] += e3*w0.y; acc[3][2] += e3*w0.z; acc[3][3] += e3*w0.w;
        acc[3][4] += e3*w1.x; acc[3][5] += e3*w1.y; acc[3][6] += e3*w1.z; acc[3][7] += e3*w1.w;
    }

#pragma unroll
    for (int m = 0; m < 4; m++) {
        int n = n0 + r0 + m * 32;
        if (n < N_NODES) {
            float* hp = &g_H[((size_t)rel * N_NODES + n) * 64 + kb];
            ((float4*)hp)[0] = make_float4(acc[m][0], acc[m][1], acc[m][2], acc[m][3]);
            ((float4*)hp)[1] = make_float4(acc[m][4], acc[m][5], acc[m][6], acc[m][7]);
        }
    }

    // s_src/s_dst via 8-lane butterfly reduce
    float ps[4], pd[4];
#pragma unroll
    for (int m = 0; m < 4; m++) {
        float a = 0.f, b = 0.f;
#pragma unroll
        for (int q = 0; q < 8; q++) { a += acc[m][q] * as[q]; b += acc[m][q] * ad[q]; }
        ps[m] = a; pd[m] = b;
    }
#pragma unroll
    for (int off = 1; off < 8; off <<= 1) {
#pragma unroll
        for (int m = 0; m < 4; m++) {
            ps[m] += __shfl_xor_sync(0xffffffffu, ps[m], off);
            pd[m] += __shfl_xor_sync(0xffffffffu, pd[m], off);
        }
    }
    if ((tid & 7) == 0) {
#pragma unroll
        for (int m = 0; m < 4; m++) {
            int n = n0 + r0 + m * 32;
            if (n < N_NODES) {
                g_Ssrc[rel * N_NODES + n] = ps[m];
                g_Sdst[rel * N_NODES + n] = pd[m];
            }
        }
    }
}

// ---------------- scatter: OUT[dst] += w*H[src], DEN[dst] += w ----------------
// 8 lanes per edge, 2 x (LDG.128 + RED.128) per lane. Covers E real edges + N self loops.
__global__ __launch_bounds__(256) void scatter_kernel(const int* __restrict__ edges, int rel0) {
    const int rel  = rel0 + blockIdx.y;
    const int t    = blockIdx.x * 256 + threadIdx.x;
    const int edge = t >> 3;
    const int sub  = threadIdx.x & 7;
    const int lane = threadIdx.x & 31;
    if (edge >= E_TOT) return;      // whole-warp uniform (E_TOT % 4 == 0)

    const int*   eb = edges + (size_t)rel * 2 * N_EDGE;
    const float* ss = g_Ssrc + rel * N_NODES;
    const float* sd = g_Sdst + rel * N_NODES;

    int s = 0, d = 0;
    float w = 0.f;
    if (sub == 0) {
        if (edge < N_EDGE) {
            s = __ldg(&eb[edge]);
            d = __ldg(&eb[N_EDGE + edge]);
        } else {
            s = d = edge - N_EDGE;      // self loop
        }
        float e = lrelu(__ldg(&ss[s]) + __ldg(&sd[d]));
        w = __expf(e);
        atomicAdd(&g_DEN[rel * N_NODES + d], w);
    }
    const int srcLane = lane & 24;
    s = __shfl_sync(0xffffffffu, s, srcLane);
    d = __shfl_sync(0xffffffffu, d, srcLane);
    w = __shfl_sync(0xffffffffu, w, srcLane);

    const size_t hb = ((size_t)rel * N_NODES + s) * 64 + sub * 4;
    const size_t ob = ((size_t)rel * N_NODES + d) * 64 + sub * 4;
    float4 h0 = *(const float4*)&g_H[hb];
    float4 h1 = *(const float4*)&g_H[hb + 32];
    float* o0 = &g_OUT[ob];
    float* o1 = &g_OUT[ob + 32];
    asm volatile("red.global.add.v4.f32 [%0], {%1,%2,%3,%4};"
                 :: "l"(o0), "f"(w * h0.x), "f"(w * h0.y),
                    "f"(w * h0.z), "f"(w * h0.w) : "memory");
    asm volatile("red.global.add.v4.f32 [%0], {%1,%2,%3,%4};"
                 :: "l"(o1), "f"(w * h1.x), "f"(w * h1.y),
                    "f"(w * h1.z), "f"(w * h1.w) : "memory");
}

// ---------------- final: normalize + bias + 2-layer MLP ----------------
// 512 threads, 128-node tile, 2 rows per thread. Dynamic smem: sA[128*65] + sB[64*64]
__global__ __launch_bounds__(512) void final_kernel(
    const float* __restrict__ emb, const float* __restrict__ bias,
    const float* __restrict__ W1, const float* __restrict__ b1,
    const float* __restrict__ W2, const float* __restrict__ b2,
    const int* __restrict__ nodes, float* __restrict__ out)
{
    extern __shared__ float smem[];
    float* sA = smem;            // 128*65
    float* sB = smem + 8320;     // 64*64
    __shared__ float sInv[128];
    __shared__ int   sNd[128];

    const int n0  = blockIdx.x * 128;
    const int tid = threadIdx.x;
    const int rp  = tid >> 3;          // 0..63 ; rows rp and rp+64
    const int cg  = tid & 7;

    if (tid < 128) {
        int nn = n0 + tid;
        sNd[tid] = (nn < N_NODES) ? nodes[nn] : -1;
    }

    float acc0[8], acc1[8];
#pragma unroll
    for (int q = 0; q < 8; q++) { acc0[q] = 0.f; acc1[q] = 0.f; }

    for (int seg = 0; seg < N_REL + 1; ++seg) {
        __syncthreads();   // prior compute done with sA/sB
        const float* w1c = W1 + (size_t)seg * 64 * 64;
        for (int i = tid; i < 1024; i += 512)
            ((float4*)sB)[i] = ((const float4*)w1c)[i];
        if (seg > 0 && tid < 128) {
            int nd = sNd[tid];
            sInv[tid] = (nd >= 0) ? (1.f / g_DEN[(seg - 1) * N_NODES + nd]) : 0.f;
        }
        __syncthreads();

        // build A tile: 2048 float4s (4 per thread)
        if (seg == 0) {
            for (int i = tid; i < 2048; i += 512) {
                int row = i >> 4, k = (i & 15) * 4;
                int nd = sNd[row];
                float4 v = make_float4(0.f, 0.f, 0.f, 0.f);
                if (nd >= 0) v = *(const float4*)&emb[(size_t)nd * 64 + k];
                sA[row * 65 + k]     = v.x; sA[row * 65 + k + 1] = v.y;
                sA[row * 65 + k + 2] = v.z; sA[row * 65 + k + 3] = v.w;
            }
        } else {
            const int r = seg - 1;
            for (int i = tid; i < 2048; i += 512) {
                int row = i >> 4, k = (i & 15) * 4;
                int nd = sNd[row];
                float4 v = make_float4(0.f, 0.f, 0.f, 0.f);
                if (nd >= 0) {
                    float4 o    = *(const float4*)&g_OUT[((size_t)r * N_NODES + nd) * 64 + k];
                    float4 bvec = *(const float4*)&bias[r * 64 + k];
                    float inv = sInv[row];
                    v.x = o.x * inv + bvec.x;
                    v.y = o.y * inv + bvec.y;
                    v.z = o.z * inv + bvec.z;
                    v.w = o.w * inv + bvec.w;
                }
                sA[row * 65 + k]     = v.x; sA[row * 65 + k + 1] = v.y;
                sA[row * 65 + k + 2] = v.z; sA[row * 65 + k + 3] = v.w;
            }
        }
        __syncthreads();

#pragma unroll 8
        for (int k = 0; k < 64; ++k) {
            float a0 = sA[rp * 65 + k];
            float a1 = sA[(rp + 64) * 65 + k];
            const float4* bp = (const float4*)&sB[k * 64 + cg * 8];
            float4 b0 = bp[0], b1v = bp[1];
            acc0[0] += a0*b0.x;  acc0[1] += a0*b0.y;  acc0[2] += a0*b0.z;  acc0[3] += a0*b0.w;
            acc0[4] += a0*b1v.x; acc0[5] += a0*b1v.y; acc0[6] += a0*b1v.z; acc0[7] += a0*b1v.w;
            acc1[0] += a1*b0.x;  acc1[1] += a1*b0.y;  acc1[2] += a1*b0.z;  acc1[3] += a1*b0.w;
            acc1[4] += a1*b1v.x; acc1[5] += a1*b1v.y; acc1[6] += a1*b1v.z; acc1[7] += a1*b1v.w;
        }
    }

    // h1 = tanh(acc + b1) -> sA ; W2 -> sB
    __syncthreads();
#pragma unroll
    for (int q = 0; q < 8; q++) {
        float bb = b1[cg * 8 + q];
        sA[rp * 65 + cg * 8 + q]        = tanhf(acc0[q] + bb);
        sA[(rp + 64) * 65 + cg * 8 + q] = tanhf(acc1[q] + bb);
    }
    for (int i = tid; i < 1024; i += 512)
        ((float4*)sB)[i] = ((const float4*)W2)[i];
    __syncthreads();

    float o0[8], o1[8];
#pragma unroll
    for (int q = 0; q < 8; q++) { o0[q] = 0.f; o1[q] = 0.f; }
#pragma unroll 8
    for (int k = 0; k < 64; ++k) {
        float a0 = sA[rp * 65 + k];
        float a1 = sA[(rp + 64) * 65 + k];
        const float4* bp = (const float4*)&sB[k * 64 + cg * 8];
        float4 b0 = bp[0], b1v = bp[1];
        o0[0] += a0*b0.x;  o0[1] += a0*b0.y;  o0[2] += a0*b0.z;  o0[3] += a0*b0.w;
        o0[4] += a0*b1v.x; o0[5] += a0*b1v.y; o0[6] += a0*b1v.z; o0[7] += a0*b1v.w;
        o1[0] += a1*b0.x;  o1[1] += a1*b0.y;  o1[2] += a1*b0.z;  o1[3] += a1*b0.w;
        o1[4] += a1*b1v.x; o1[5] += a1*b1v.y; o1[6] += a1*b1v.z; o1[7] += a1*b1v.w;
    }

    int nn0 = n0 + rp, nn1 = n0 + rp + 64;
    if (nn0 < N_NODES) {
        float4 v0 = make_float4(o0[0]+b2[cg*8+0], o0[1]+b2[cg*8+1], o0[2]+b2[cg*8+2], o0[3]+b2[cg*8+3]);
        float4 v1 = make_float4(o0[4]+b2[cg*8+4], o0[5]+b2[cg*8+5], o0[6]+b2[cg*8+6], o0[7]+b2[cg*8+7]);
        ((float4*)&out[(size_t)nn0 * 64 + cg * 8])[0] = v0;
        ((float4*)&out[(size_t)nn0 * 64 + cg * 8])[1] = v1;
    }
    if (nn1 < N_NODES) {
        float4 v0 = make_float4(o1[0]+b2[cg*8+0], o1[1]+b2[cg*8+1], o1[2]+b2[cg*8+2], o1[3]+b2[cg*8+3]);
        float4 v1 = make_float4(o1[4]+b2[cg*8+4], o1[5]+b2[cg*8+5], o1[6]+b2[cg*8+6], o1[7]+b2[cg*8+7]);
        ((float4*)&out[(size_t)nn1 * 64 + cg * 8])[0] = v0;
        ((float4*)&out[(size_t)nn1 * 64 + cg * 8])[1] = v1;
    }
}

// ---------------- launch ----------------
extern "C" void kernel_launch(void* const* d_in, const int* in_sizes, int n_in,
                              void* d_out, int out_size) {
    const float* emb     = (const float*)d_in[0];
    const float* W       = (const float*)d_in[1];
    const float* att_src = (const float*)d_in[2];
    const float* att_dst = (const float*)d_in[3];
    const float* bias    = (const float*)d_in[4];
    const float* W1      = (const float*)d_in[5];
    const float* b1      = (const float*)d_in[6];
    const float* W2      = (const float*)d_in[7];
    const float* b2      = (const float*)d_in[8];
    const int*   edges   = (const int*)d_in[9];
    const int*   nodes   = (const int*)d_in[10];
    float*       out     = (float*)d_out;

    const int GEMM_SMEM  = (4096 + 128 * 65) * 4;          // 49664
    const int FINAL_SMEM = (128 * 65 + 64 * 64) * 4;       // 49664
    cudaFuncSetAttribute(gemm_s_kernel, cudaFuncAttributeMaxDynamicSharedMemorySize, GEMM_SMEM);
    cudaFuncSetAttribute(final_kernel,  cudaFuncAttributeMaxDynamicSharedMemorySize, FINAL_SMEM);

    const size_t tot4 = (size_t)N_REL * N_NODES * HID / 4;
    zero_kernel<<<(unsigned)((tot4 + 255) / 256), 256>>>();

    dim3 g1((N_NODES + 127) / 128, N_REL);
    gemm_s_kernel<<<g1, 256, GEMM_SMEM>>>(emb, W, att_src, att_dst);

    // 8 lanes per (edge|self-loop)
    const int sblocks = (E_TOT * 8 + 255) / 256;   // 7188
    for (int r = 0; r < N_REL; r += 2) {
        dim3 gs(sblocks, 2);
        scatter_kernel<<<gs, 256>>>(edges, r);
    }

    final_kernel<<<(N_NODES + 127) / 128, 512, FINAL_SMEM>>>(emb, bias, W1, b1, W2, b2, nodes, out);
}

// round 5
// speedup vs baseline: 1.7101x; 1.1493x over previous
#include <cuda_runtime.h>
#include <math.h>

#define N_NODES 30000
#define N_REL   38
#define N_EDGE  200000
#define HID     64
#define E_TOT   (N_EDGE + N_NODES)   // real edges + self loops

// packed fp32x2 helpers (Blackwell FFMA2 — ptxas never auto-generates these)
#define FMA2(acc, a, b) asm("fma.rn.f32x2 %0, %1, %2, %0;" : "+l"(acc) : "l"(a), "l"(b))
#define PACK2(out, x)   asm("mov.b64 %0, {%1, %1};" : "=l"(out) : "f"(x))
#define UNPK2(lo, hi, in) asm("mov.b64 {%0, %1}, %2;" : "=f"(lo), "=f"(hi) : "l"(in))

// ---------------- scratch (static __device__ — no allocation allowed) ----------------
__device__ float g_H  [(size_t)N_REL * N_NODES * HID];   // 291.84 MB
__device__ float g_OUT[(size_t)N_REL * N_NODES * HID];   // unnormalized Σ w·h
__device__ float g_Ssrc[N_REL * N_NODES];
__device__ float g_Sdst[N_REL * N_NODES];
__device__ float g_DEN [N_REL * N_NODES];                // Σ w (incl. self loop)

__device__ __forceinline__ float lrelu(float x) { return x > 0.f ? x : 0.2f * x; }

// ---------------- zero OUT + DEN ----------------
__global__ void zero_kernel() {
    size_t i = (size_t)blockIdx.x * blockDim.x + threadIdx.x;
    size_t tot4 = (size_t)N_REL * N_NODES * HID / 4;
    if (i < tot4) ((float4*)g_OUT)[i] = make_float4(0.f, 0.f, 0.f, 0.f);
    if (i < (size_t)N_REL * N_NODES) g_DEN[i] = 0.f;
}

// ---------------- per-relation GEMM H = emb @ W[r], fused s_src/s_dst ----------------
// 256 threads, 128-node x 64-hid tile, 4 rows/thread, FFMA2 packed accumulators.
__global__ __launch_bounds__(256) void gemm_s_kernel(
    const float* __restrict__ emb, const float* __restrict__ W,
    const float* __restrict__ att_src, const float* __restrict__ att_dst, int rel0)
{
    extern __shared__ float smem[];
    float* sW = smem;            // 64*64
    float* sE = smem + 4096;     // 128*65

    const int rel = rel0 + blockIdx.y;
    const int n0  = blockIdx.x * 128;
    const int tid = threadIdx.x;

    const float* Wr = W + rel * 4096;
    for (int i = tid; i < 1024; i += 256)
        ((float4*)sW)[i] = ((const float4*)Wr)[i];
    for (int i = tid; i < 2048; i += 256) {
        int row = i >> 4, k = (i & 15) * 4;
        int n = n0 + row;
        float4 v = make_float4(0.f, 0.f, 0.f, 0.f);
        if (n < N_NODES) v = *(const float4*)&emb[(size_t)n * 64 + k];
        sE[row * 65 + k]     = v.x; sE[row * 65 + k + 1] = v.y;
        sE[row * 65 + k + 2] = v.z; sE[row * 65 + k + 3] = v.w;
    }

    const int kb = (tid & 7) * 8;
    float as[8], ad[8];
#pragma unroll
    for (int q = 0; q < 8; q++) {
        as[q] = att_src[rel * 64 + kb + q];
        ad[q] = att_dst[rel * 64 + kb + q];
    }
    __syncthreads();

    const int r0 = tid >> 3;          // 0..31 ; rows r0, +32, +64, +96
    unsigned long long accp[4][4];    // 4 rows x 4 col-pairs (fp32x2)
#pragma unroll
    for (int m = 0; m < 4; m++)
#pragma unroll
        for (int p = 0; p < 4; p++) accp[m][p] = 0ULL;

#pragma unroll 4
    for (int j = 0; j < 64; ++j) {
        float e0 = sE[(r0      ) * 65 + j];
        float e1 = sE[(r0 + 32 ) * 65 + j];
        float e2 = sE[(r0 + 64 ) * 65 + j];
        float e3 = sE[(r0 + 96 ) * 65 + j];
        unsigned long long ep0, ep1, ep2, ep3;
        PACK2(ep0, e0); PACK2(ep1, e1); PACK2(ep2, e2); PACK2(ep3, e3);
        const ulonglong2* wv = (const ulonglong2*)&sW[j * 64 + kb];
        ulonglong2 wA = wv[0], wB = wv[1];   // col pairs (kb,kb+1)(kb+2,kb+3)(+4,+5)(+6,+7)
        FMA2(accp[0][0], ep0, wA.x); FMA2(accp[0][1], ep0, wA.y);
        FMA2(accp[0][2], ep0, wB.x); FMA2(accp[0][3], ep0, wB.y);
        FMA2(accp[1][0], ep1, wA.x); FMA2(accp[1][1], ep1, wA.y);
        FMA2(accp[1][2], ep1, wB.x); FMA2(accp[1][3], ep1, wB.y);
        FMA2(accp[2][0], ep2, wA.x); FMA2(accp[2][1], ep2, wA.y);
        FMA2(accp[2][2], ep2, wB.x); FMA2(accp[2][3], ep2, wB.y);
        FMA2(accp[3][0], ep3, wA.x); FMA2(accp[3][1], ep3, wA.y);
        FMA2(accp[3][2], ep3, wB.x); FMA2(accp[3][3], ep3, wB.y);
    }

#pragma unroll
    for (int m = 0; m < 4; m++) {
        int n = n0 + r0 + m * 32;
        if (n < N_NODES) {
            ulonglong2* hp = (ulonglong2*)&g_H[((size_t)rel * N_NODES + n) * 64 + kb];
            hp[0] = make_ulonglong2(accp[m][0], accp[m][1]);
            hp[1] = make_ulonglong2(accp[m][2], accp[m][3]);
        }
    }

    // s_src/s_dst: unpack + dot + 8-lane butterfly reduce
    float ps[4], pd[4];
#pragma unroll
    for (int m = 0; m < 4; m++) {
        float a = 0.f, b = 0.f;
#pragma unroll
        for (int p = 0; p < 4; p++) {
            float lo, hi;
            UNPK2(lo, hi, accp[m][p]);
            a += lo * as[p * 2] + hi * as[p * 2 + 1];
            b += lo * ad[p * 2] + hi * ad[p * 2 + 1];
        }
        ps[m] = a; pd[m] = b;
    }
#pragma unroll
    for (int off = 1; off < 8; off <<= 1) {
#pragma unroll
        for (int m = 0; m < 4; m++) {
            ps[m] += __shfl_xor_sync(0xffffffffu, ps[m], off);
            pd[m] += __shfl_xor_sync(0xffffffffu, pd[m], off);
        }
    }
    if ((tid & 7) == 0) {
#pragma unroll
        for (int m = 0; m < 4; m++) {
            int n = n0 + r0 + m * 32;
            if (n < N_NODES) {
                g_Ssrc[rel * N_NODES + n] = ps[m];
                g_Sdst[rel * N_NODES + n] = pd[m];
            }
        }
    }
}

// ---------------- scatter: OUT[dst] += w*H[src], DEN[dst] += w ----------------
__global__ __launch_bounds__(256) void scatter_kernel(const int* __restrict__ edges, int rel0) {
    const int rel  = rel0 + blockIdx.y;
    const int t    = blockIdx.x * 256 + threadIdx.x;
    const int edge = t >> 3;
    const int sub  = threadIdx.x & 7;
    const int lane = threadIdx.x & 31;
    if (edge >= E_TOT) return;

    const int*   eb = edges + (size_t)rel * 2 * N_EDGE;
    const float* ss = g_Ssrc + rel * N_NODES;
    const float* sd = g_Sdst + rel * N_NODES;

    int s = 0, d = 0;
    float w = 0.f;
    if (sub == 0) {
        if (edge < N_EDGE) {
            s = __ldg(&eb[edge]);
            d = __ldg(&eb[N_EDGE + edge]);
        } else {
            s = d = edge - N_EDGE;      // self loop
        }
        float e = lrelu(__ldg(&ss[s]) + __ldg(&sd[d]));
        w = __expf(e);
        atomicAdd(&g_DEN[rel * N_NODES + d], w);
    }
    const int srcLane = lane & 24;
    s = __shfl_sync(0xffffffffu, s, srcLane);
    d = __shfl_sync(0xffffffffu, d, srcLane);
    w = __shfl_sync(0xffffffffu, w, srcLane);

    const size_t hb = ((size_t)rel * N_NODES + s) * 64 + sub * 4;
    const size_t ob = ((size_t)rel * N_NODES + d) * 64 + sub * 4;
    float4 h0 = *(const float4*)&g_H[hb];
    float4 h1 = *(const float4*)&g_H[hb + 32];
    float* o0 = &g_OUT[ob];
    float* o1 = &g_OUT[ob + 32];
    asm volatile("red.global.add.v4.f32 [%0], {%1,%2,%3,%4};"
                 :: "l"(o0), "f"(w * h0.x), "f"(w * h0.y),
                    "f"(w * h0.z), "f"(w * h0.w) : "memory");
    asm volatile("red.global.add.v4.f32 [%0], {%1,%2,%3,%4};"
                 :: "l"(o1), "f"(w * h1.x), "f"(w * h1.y),
                    "f"(w * h1.z), "f"(w * h1.w) : "memory");
}

// ---------------- final: normalize + bias + 2-layer MLP ----------------
// 256 threads, 128-node tile, 4 rows/thread, FFMA2.
__global__ __launch_bounds__(256) void final_kernel(
    const float* __restrict__ emb, const float* __restrict__ bias,
    const float* __restrict__ W1, const float* __restrict__ b1,
    const float* __restrict__ W2, const float* __restrict__ b2,
    const int* __restrict__ nodes, float* __restrict__ out)
{
    extern __shared__ float smem[];
    float* sA = smem;            // 128*65
    float* sB = smem + 8320;     // 64*64
    __shared__ float sInv[128];
    __shared__ int   sNd[128];

    const int n0  = blockIdx.x * 128;
    const int tid = threadIdx.x;
    const int rp  = tid >> 3;          // 0..31 ; rows rp, +32, +64, +96
    const int cg  = tid & 7;
    const int kb  = cg * 8;

    if (tid < 128) {
        int nn = n0 + tid;
        sNd[tid] = (nn < N_NODES) ? nodes[nn] : -1;
    }

    unsigned long long accp[4][4];
#pragma unroll
    for (int m = 0; m < 4; m++)
#pragma unroll
        for (int p = 0; p < 4; p++) accp[m][p] = 0ULL;

    for (int seg = 0; seg < N_REL + 1; ++seg) {
        __syncthreads();   // prior compute done with sA/sB
        const float* w1c = W1 + (size_t)seg * 64 * 64;
        for (int i = tid; i < 1024; i += 256)
            ((float4*)sB)[i] = ((const float4*)w1c)[i];
        if (seg > 0 && tid < 128) {
            int nd = sNd[tid];
            sInv[tid] = (nd >= 0) ? (1.f / g_DEN[(seg - 1) * N_NODES + nd]) : 0.f;
        }
        __syncthreads();

        // build A tile: 2048 float4s (8 per thread)
        if (seg == 0) {
            for (int i = tid; i < 2048; i += 256) {
                int row = i >> 4, k = (i & 15) * 4;
                int nd = sNd[row];
                float4 v = make_float4(0.f, 0.f, 0.f, 0.f);
                if (nd >= 0) v = *(const float4*)&emb[(size_t)nd * 64 + k];
                sA[row * 65 + k]     = v.x; sA[row * 65 + k + 1] = v.y;
                sA[row * 65 + k + 2] = v.z; sA[row * 65 + k + 3] = v.w;
            }
        } else {
            const int r = seg - 1;
            for (int i = tid; i < 2048; i += 256) {
                int row = i >> 4, k = (i & 15) * 4;
                int nd = sNd[row];
                float4 v = make_float4(0.f, 0.f, 0.f, 0.f);
                if (nd >= 0) {
                    float4 o    = *(const float4*)&g_OUT[((size_t)r * N_NODES + nd) * 64 + k];
                    float4 bvec = *(const float4*)&bias[r * 64 + k];
                    float inv = sInv[row];
                    v.x = o.x * inv + bvec.x;
                    v.y = o.y * inv + bvec.y;
                    v.z = o.z * inv + bvec.z;
                    v.w = o.w * inv + bvec.w;
                }
                sA[row * 65 + k]     = v.x; sA[row * 65 + k + 1] = v.y;
                sA[row * 65 + k + 2] = v.z; sA[row * 65 + k + 3] = v.w;
            }
        }
        __syncthreads();

#pragma unroll 4
        for (int k = 0; k < 64; ++k) {
            float a0 = sA[(rp      ) * 65 + k];
            float a1 = sA[(rp + 32 ) * 65 + k];
            float a2 = sA[(rp + 64 ) * 65 + k];
            float a3 = sA[(rp + 96 ) * 65 + k];
            unsigned long long p0, p1, p2, p3;
            PACK2(p0, a0); PACK2(p1, a1); PACK2(p2, a2); PACK2(p3, a3);
            const ulonglong2* bp = (const ulonglong2*)&sB[k * 64 + kb];
            ulonglong2 bA = bp[0], bB = bp[1];
            FMA2(accp[0][0], p0, bA.x); FMA2(accp[0][1], p0, bA.y);
            FMA2(accp[0][2], p0, bB.x); FMA2(accp[0][3], p0, bB.y);
            FMA2(accp[1][0], p1, bA.x); FMA2(accp[1][1], p1, bA.y);
            FMA2(accp[1][2], p1, bB.x); FMA2(accp[1][3], p1, bB.y);
            FMA2(accp[2][0], p2, bA.x); FMA2(accp[2][1], p2, bA.y);
            FMA2(accp[2][2], p2, bB.x); FMA2(accp[2][3], p2, bB.y);
            FMA2(accp[3][0], p3, bA.x); FMA2(accp[3][1], p3, bA.y);
            FMA2(accp[3][2], p3, bB.x); FMA2(accp[3][3], p3, bB.y);
        }
    }

    // h1 = tanh(acc + b1) -> sA ; W2 -> sB
    __syncthreads();
    {
        float bb[8];
#pragma unroll
        for (int q = 0; q < 8; q++) bb[q] = b1[kb + q];
#pragma unroll
        for (int m = 0; m < 4; m++) {
            int row = rp + m * 32;
#pragma unroll
            for (int p = 0; p < 4; p++) {
                float lo, hi;
                UNPK2(lo, hi, accp[m][p]);
                sA[row * 65 + kb + p * 2]     = tanhf(lo + bb[p * 2]);
                sA[row * 65 + kb + p * 2 + 1] = tanhf(hi + bb[p * 2 + 1]);
            }
        }
    }
    for (int i = tid; i < 1024; i += 256)
        ((float4*)sB)[i] = ((const float4*)W2)[i];
    __syncthreads();

    unsigned long long op[4][4];
#pragma unroll
    for (int m = 0; m < 4; m++)
#pragma unroll
        for (int p = 0; p < 4; p++) op[m][p] = 0ULL;
#pragma unroll 4
    for (int k = 0; k < 64; ++k) {
        float a0 = sA[(rp      ) * 65 + k];
        float a1 = sA[(rp + 32 ) * 65 + k];
        float a2 = sA[(rp + 64 ) * 65 + k];
        float a3 = sA[(rp + 96 ) * 65 + k];
        unsigned long long p0, p1, p2, p3;
        PACK2(p0, a0); PACK2(p1, a1); PACK2(p2, a2); PACK2(p3, a3);
        const ulonglong2* bp = (const ulonglong2*)&sB[k * 64 + kb];
        ulonglong2 bA = bp[0], bB = bp[1];
        FMA2(op[0][0], p0, bA.x); FMA2(op[0][1], p0, bA.y);
        FMA2(op[0][2], p0, bB.x); FMA2(op[0][3], p0, bB.y);
        FMA2(op[1][0], p1, bA.x); FMA2(op[1][1], p1, bA.y);
        FMA2(op[1][2], p1, bB.x); FMA2(op[1][3], p1, bB.y);
        FMA2(op[2][0], p2, bA.x); FMA2(op[2][1], p2, bA.y);
        FMA2(op[2][2], p2, bB.x); FMA2(op[2][3], p2, bB.y);
        FMA2(op[3][0], p3, bA.x); FMA2(op[3][1], p3, bA.y);
        FMA2(op[3][2], p3, bB.x); FMA2(op[3][3], p3, bB.y);
    }

    float b2v[8];
#pragma unroll
    for (int q = 0; q < 8; q++) b2v[q] = b2[kb + q];
#pragma unroll
    for (int m = 0; m < 4; m++) {
        int nn = n0 + rp + m * 32;
        if (nn < N_NODES) {
            float r[8];
#pragma unroll
            for (int p = 0; p < 4; p++) {
                float lo, hi;
                UNPK2(lo, hi, op[m][p]);
                r[p * 2]     = lo + b2v[p * 2];
                r[p * 2 + 1] = hi + b2v[p * 2 + 1];
            }
            float4* o = (float4*)&out[(size_t)nn * 64 + kb];
            o[0] = make_float4(r[0], r[1], r[2], r[3]);
            o[1] = make_float4(r[4], r[5], r[6], r[7]);
        }
    }
}

// ---------------- launch ----------------
extern "C" void kernel_launch(void* const* d_in, const int* in_sizes, int n_in,
                              void* d_out, int out_size) {
    const float* emb     = (const float*)d_in[0];
    const float* W       = (const float*)d_in[1];
    const float* att_src = (const float*)d_in[2];
    const float* att_dst = (const float*)d_in[3];
    const float* bias    = (const float*)d_in[4];
    const float* W1      = (const float*)d_in[5];
    const float* b1      = (const float*)d_in[6];
    const float* W2      = (const float*)d_in[7];
    const float* b2      = (const float*)d_in[8];
    const int*   edges   = (const int*)d_in[9];
    const int*   nodes   = (const int*)d_in[10];
    float*       out     = (float*)d_out;

    const int GEMM_SMEM  = (4096 + 128 * 65) * 4;          // 49664
    const int FINAL_SMEM = (128 * 65 + 64 * 64) * 4;       // 49664
    cudaFuncSetAttribute(gemm_s_kernel, cudaFuncAttributeMaxDynamicSharedMemorySize, GEMM_SMEM);
    cudaFuncSetAttribute(final_kernel,  cudaFuncAttributeMaxDynamicSharedMemorySize, FINAL_SMEM);

    const size_t tot4 = (size_t)N_REL * N_NODES * HID / 4;
    zero_kernel<<<(unsigned)((tot4 + 255) / 256), 256>>>();

    // 5 gemm launches (rel chunks 8,8,8,8,6) — also puts a gemm at ncu's capture index 5
    const int nb = (N_NODES + 127) / 128;
    for (int c = 0; c < 5; ++c) {
        int r0 = c * 8;
        int nr = (c == 4) ? 6 : 8;
        dim3 g1(nb, nr);
        gemm_s_kernel<<<g1, 256, GEMM_SMEM>>>(emb, W, att_src, att_dst, r0);
    }

    // 8 lanes per (edge|self-loop)
    const int sblocks = (E_TOT * 8 + 255) / 256;   // 7188
    for (int r = 0; r < N_REL; r += 2) {
        dim3 gs(sblocks, 2);
        scatter_kernel<<<gs, 256>>>(edges, r);
    }

    final_kernel<<<nb, 256, FINAL_SMEM>>>(emb, bias, W1, b1, W2, b2, nodes, out);
}

// round 6
// speedup vs baseline: 1.8540x; 1.0841x over previous
#include <cuda_runtime.h>
#include <math.h>

#define N_NODES 30000
#define N_REL   38
#define N_EDGE  200000
#define HID     64
#define E_TOT   (N_EDGE + N_NODES)
#define PAD     68                    // smem row pitch (floats): 16B-aligned, conflict-free
#define N_CHUNK 5                     // final_acc seg chunks (8,8,8,8,7)

// packed fp32x2 helpers (Blackwell FFMA2 — ptxas never auto-generates these)
#define FMA2(acc, a, b) asm("fma.rn.f32x2 %0, %1, %2, %0;" : "+l"(acc) : "l"(a), "l"(b))
#define PACK2(out, x)   asm("mov.b64 %0, {%1, %1};" : "=l"(out) : "f"(x))
#define UNPK2(lo, hi, in) asm("mov.b64 {%0, %1}, %2;" : "=f"(lo), "=f"(hi) : "l"(in))

// ---------------- scratch ----------------
__device__ float g_H  [(size_t)N_REL * N_NODES * HID];
__device__ float g_OUT[(size_t)N_REL * N_NODES * HID];
__device__ float g_Ssrc[N_REL * N_NODES];
__device__ float g_Sdst[N_REL * N_NODES];
__device__ float g_DEN [N_REL * N_NODES];
__device__ float g_PREP[N_CHUNK][(size_t)N_NODES * HID];   // pre-tanh partial sums

__device__ __forceinline__ float lrelu(float x) { return x > 0.f ? x : 0.2f * x; }

// ---------------- zero OUT + DEN ----------------
__global__ void zero_kernel() {
    size_t i = (size_t)blockIdx.x * blockDim.x + threadIdx.x;
    size_t tot4 = (size_t)N_REL * N_NODES * HID / 4;
    if (i < tot4) ((float4*)g_OUT)[i] = make_float4(0.f, 0.f, 0.f, 0.f);
    if (i < (size_t)N_REL * N_NODES) g_DEN[i] = 0.f;
}

// vectorized 128x64 @ 64x64 mainloop body: sA rows pitch PAD, sB 64x64.
// Thread: 4 rows (r0+32m), 8 cols (kb..kb+7). Accumulates into accp[4][4] (fp32x2).
__device__ __forceinline__ void mma_tile_128(
    const float* sA, const float* sB, int r0, int kb, unsigned long long accp[4][4])
{
#pragma unroll 4
    for (int j4 = 0; j4 < 16; ++j4) {
        float4 E0 = *(const float4*)&sA[(r0      ) * PAD + j4 * 4];
        float4 E1 = *(const float4*)&sA[(r0 + 32 ) * PAD + j4 * 4];
        float4 E2 = *(const float4*)&sA[(r0 + 64 ) * PAD + j4 * 4];
        float4 E3 = *(const float4*)&sA[(r0 + 96 ) * PAD + j4 * 4];
#pragma unroll
        for (int jj = 0; jj < 4; ++jj) {
            unsigned long long ep0, ep1, ep2, ep3;
            PACK2(ep0, ((const float*)&E0)[jj]);
            PACK2(ep1, ((const float*)&E1)[jj]);
            PACK2(ep2, ((const float*)&E2)[jj]);
            PACK2(ep3, ((const float*)&E3)[jj]);
            const ulonglong2* wv = (const ulonglong2*)&sB[(j4 * 4 + jj) * 64 + kb];
            ulonglong2 wA = wv[0], wB = wv[1];
            FMA2(accp[0][0], ep0, wA.x); FMA2(accp[0][1], ep0, wA.y);
            FMA2(accp[0][2], ep0, wB.x); FMA2(accp[0][3], ep0, wB.y);
            FMA2(accp[1][0], ep1, wA.x); FMA2(accp[1][1], ep1, wA.y);
            FMA2(accp[1][2], ep1, wB.x); FMA2(accp[1][3], ep1, wB.y);
            FMA2(accp[2][0], ep2, wA.x); FMA2(accp[2][1], ep2, wA.y);
            FMA2(accp[2][2], ep2, wB.x); FMA2(accp[2][3], ep2, wB.y);
            FMA2(accp[3][0], ep3, wA.x); FMA2(accp[3][1], ep3, wA.y);
            FMA2(accp[3][2], ep3, wB.x); FMA2(accp[3][3], ep3, wB.y);
        }
    }
}

// ---------------- per-relation GEMM H = emb @ W[r], fused s_src/s_dst ----------------
__global__ __launch_bounds__(256) void gemm_s_kernel(
    const float* __restrict__ emb, const float* __restrict__ W,
    const float* __restrict__ att_src, const float* __restrict__ att_dst, int rel0)
{
    extern __shared__ float smem[];
    float* sW = smem;            // 64*64
    float* sE = smem + 4096;     // 128*PAD

    const int rel = rel0 + blockIdx.y;
    const int n0  = blockIdx.x * 128;
    const int tid = threadIdx.x;

    const float* Wr = W + rel * 4096;
    for (int i = tid; i < 1024; i += 256)
        ((float4*)sW)[i] = ((const float4*)Wr)[i];
    for (int i = tid; i < 2048; i += 256) {
        int row = i >> 4, k = (i & 15) * 4;
        int n = n0 + row;
        float4 v = make_float4(0.f, 0.f, 0.f, 0.f);
        if (n < N_NODES) v = *(const float4*)&emb[(size_t)n * 64 + k];
        *(float4*)&sE[row * PAD + k] = v;
    }

    const int kb = (tid & 7) * 8;
    float as[8], ad[8];
#pragma unroll
    for (int q = 0; q < 8; q++) {
        as[q] = att_src[rel * 64 + kb + q];
        ad[q] = att_dst[rel * 64 + kb + q];
    }
    __syncthreads();

    const int r0 = tid >> 3;
    unsigned long long accp[4][4];
#pragma unroll
    for (int m = 0; m < 4; m++)
#pragma unroll
        for (int p = 0; p < 4; p++) accp[m][p] = 0ULL;

    mma_tile_128(sE, sW, r0, kb, accp);

#pragma unroll
    for (int m = 0; m < 4; m++) {
        int n = n0 + r0 + m * 32;
        if (n < N_NODES) {
            ulonglong2* hp = (ulonglong2*)&g_H[((size_t)rel * N_NODES + n) * 64 + kb];
            hp[0] = make_ulonglong2(accp[m][0], accp[m][1]);
            hp[1] = make_ulonglong2(accp[m][2], accp[m][3]);
        }
    }

    float ps[4], pd[4];
#pragma unroll
    for (int m = 0; m < 4; m++) {
        float a = 0.f, b = 0.f;
#pragma unroll
        for (int p = 0; p < 4; p++) {
            float lo, hi;
            UNPK2(lo, hi, accp[m][p]);
            a += lo * as[p * 2] + hi * as[p * 2 + 1];
            b += lo * ad[p * 2] + hi * ad[p * 2 + 1];
        }
        ps[m] = a; pd[m] = b;
    }
#pragma unroll
    for (int off = 1; off < 8; off <<= 1) {
#pragma unroll
        for (int m = 0; m < 4; m++) {
            ps[m] += __shfl_xor_sync(0xffffffffu, ps[m], off);
            pd[m] += __shfl_xor_sync(0xffffffffu, pd[m], off);
        }
    }
    if ((tid & 7) == 0) {
#pragma unroll
        for (int m = 0; m < 4; m++) {
            int n = n0 + r0 + m * 32;
            if (n < N_NODES) {
                g_Ssrc[rel * N_NODES + n] = ps[m];
                g_Sdst[rel * N_NODES + n] = pd[m];
            }
        }
    }
}

// ---------------- scatter: OUT[dst] += w*H[src], DEN[dst] += w ----------------
__global__ __launch_bounds__(256) void scatter_kernel(const int* __restrict__ edges, int rel0) {
    const int rel  = rel0 + blockIdx.y;
    const int t    = blockIdx.x * 256 + threadIdx.x;
    const int edge = t >> 3;
    const int sub  = threadIdx.x & 7;
    const int lane = threadIdx.x & 31;
    if (edge >= E_TOT) return;

    const int*   eb = edges + (size_t)rel * 2 * N_EDGE;
    const float* ss = g_Ssrc + rel * N_NODES;
    const float* sd = g_Sdst + rel * N_NODES;

    int s = 0, d = 0;
    float w = 0.f;
    if (sub == 0) {
        if (edge < N_EDGE) {
            s = __ldg(&eb[edge]);
            d = __ldg(&eb[N_EDGE + edge]);
        } else {
            s = d = edge - N_EDGE;
        }
        float e = lrelu(__ldg(&ss[s]) + __ldg(&sd[d]));
        w = __expf(e);
        atomicAdd(&g_DEN[rel * N_NODES + d], w);
    }
    const int srcLane = lane & 24;
    s = __shfl_sync(0xffffffffu, s, srcLane);
    d = __shfl_sync(0xffffffffu, d, srcLane);
    w = __shfl_sync(0xffffffffu, w, srcLane);

    const size_t hb = ((size_t)rel * N_NODES + s) * 64 + sub * 4;
    const size_t ob = ((size_t)rel * N_NODES + d) * 64 + sub * 4;
    float4 h0 = *(const float4*)&g_H[hb];
    float4 h1 = *(const float4*)&g_H[hb + 32];
    float* o0 = &g_OUT[ob];
    float* o1 = &g_OUT[ob + 32];
    asm volatile("red.global.add.v4.f32 [%0], {%1,%2,%3,%4};"
                 :: "l"(o0), "f"(w * h0.x), "f"(w * h0.y),
                    "f"(w * h0.z), "f"(w * h0.w) : "memory");
    asm volatile("red.global.add.v4.f32 [%0], {%1,%2,%3,%4};"
                 :: "l"(o1), "f"(w * h1.x), "f"(w * h1.y),
                    "f"(w * h1.z), "f"(w * h1.w) : "memory");
}

// ---------------- final_acc: partial pre-tanh sums over an 8-seg chunk ----------------
__global__ __launch_bounds__(256) void final_acc(
    const float* __restrict__ emb, const float* __restrict__ bias,
    const float* __restrict__ W1, const int* __restrict__ nodes)
{
    extern __shared__ float smem[];
    float* sA = smem;            // 128*PAD
    float* sB = smem + 128 * PAD;
    __shared__ float sInv[128];
    __shared__ int   sNd[128];

    const int chunk = blockIdx.y;
    const int seg0  = chunk * 8;
    const int seg1  = (seg0 + 8 < N_REL + 1) ? seg0 + 8 : N_REL + 1;
    const int n0  = blockIdx.x * 128;
    const int tid = threadIdx.x;
    const int r0  = tid >> 3;
    const int kb  = (tid & 7) * 8;

    if (tid < 128) {
        int nn = n0 + tid;
        sNd[tid] = (nn < N_NODES) ? nodes[nn] : -1;
    }

    unsigned long long accp[4][4];
#pragma unroll
    for (int m = 0; m < 4; m++)
#pragma unroll
        for (int p = 0; p < 4; p++) accp[m][p] = 0ULL;

    for (int seg = seg0; seg < seg1; ++seg) {
        __syncthreads();
        const float* w1c = W1 + (size_t)seg * 4096;
        for (int i = tid; i < 1024; i += 256)
            ((float4*)sB)[i] = ((const float4*)w1c)[i];
        if (seg > 0 && tid < 128) {
            int nd = sNd[tid];
            sInv[tid] = (nd >= 0) ? (1.f / g_DEN[(seg - 1) * N_NODES + nd]) : 0.f;
        }
        __syncthreads();

        if (seg == 0) {
            for (int i = tid; i < 2048; i += 256) {
                int row = i >> 4, k = (i & 15) * 4;
                int nd = sNd[row];
                float4 v = make_float4(0.f, 0.f, 0.f, 0.f);
                if (nd >= 0) v = *(const float4*)&emb[(size_t)nd * 64 + k];
                *(float4*)&sA[row * PAD + k] = v;
            }
        } else {
            const int r = seg - 1;
            for (int i = tid; i < 2048; i += 256) {
                int row = i >> 4, k = (i & 15) * 4;
                int nd = sNd[row];
                float4 v = make_float4(0.f, 0.f, 0.f, 0.f);
                if (nd >= 0) {
                    float4 o    = *(const float4*)&g_OUT[((size_t)r * N_NODES + nd) * 64 + k];
                    float4 bvec = *(const float4*)&bias[r * 64 + k];
                    float inv = sInv[row];
                    v.x = o.x * inv + bvec.x;
                    v.y = o.y * inv + bvec.y;
                    v.z = o.z * inv + bvec.z;
                    v.w = o.w * inv + bvec.w;
                }
                *(float4*)&sA[row * PAD + k] = v;
            }
        }
        __syncthreads();

        mma_tile_128(sA, sB, r0, kb, accp);
    }

    float* prep = g_PREP[chunk];
#pragma unroll
    for (int m = 0; m < 4; m++) {
        int nn = n0 + r0 + m * 32;
        if (nn < N_NODES) {
            ulonglong2* pp = (ulonglong2*)&prep[(size_t)nn * 64 + kb];
            pp[0] = make_ulonglong2(accp[m][0], accp[m][1]);
            pp[1] = make_ulonglong2(accp[m][2], accp[m][3]);
        }
    }
}

// ---------------- final_finish: sum partials, tanh, @W2 + b2 ----------------
__global__ __launch_bounds__(256) void final_finish(
    const float* __restrict__ b1, const float* __restrict__ W2,
    const float* __restrict__ b2, float* __restrict__ out)
{
    extern __shared__ float smem[];
    float* sA = smem;            // 128*PAD
    float* sB = smem + 128 * PAD;

    const int n0  = blockIdx.x * 128;
    const int tid = threadIdx.x;
    const int r0  = tid >> 3;
    const int kb  = (tid & 7) * 8;

    for (int i = tid; i < 1024; i += 256)
        ((float4*)sB)[i] = ((const float4*)W2)[i];

    // sA = tanh(sum partials + b1)
    for (int i = tid; i < 2048; i += 256) {
        int row = i >> 4, k = (i & 15) * 4;
        int nn = n0 + row;
        float4 v = make_float4(0.f, 0.f, 0.f, 0.f);
        if (nn < N_NODES) {
            size_t off = (size_t)nn * 64 + k;
#pragma unroll
            for (int c = 0; c < N_CHUNK; ++c) {
                float4 p = *(const float4*)&g_PREP[c][off];
                v.x += p.x; v.y += p.y; v.z += p.z; v.w += p.w;
            }
            float4 bb = *(const float4*)&b1[k];
            v.x = tanhf(v.x + bb.x); v.y = tanhf(v.y + bb.y);
            v.z = tanhf(v.z + bb.z); v.w = tanhf(v.w + bb.w);
        }
        *(float4*)&sA[row * PAD + k] = v;
    }
    __syncthreads();

    unsigned long long accp[4][4];
#pragma unroll
    for (int m = 0; m < 4; m++)
#pragma unroll
        for (int p = 0; p < 4; p++) accp[m][p] = 0ULL;

    mma_tile_128(sA, sB, r0, kb, accp);

    float b2v[8];
#pragma unroll
    for (int q = 0; q < 8; q++) b2v[q] = b2[kb + q];
#pragma unroll
    for (int m = 0; m < 4; m++) {
        int nn = n0 + r0 + m * 32;
        if (nn < N_NODES) {
            float r[8];
#pragma unroll
            for (int p = 0; p < 4; p++) {
                float lo, hi;
                UNPK2(lo, hi, accp[m][p]);
                r[p * 2]     = lo + b2v[p * 2];
                r[p * 2 + 1] = hi + b2v[p * 2 + 1];
            }
            float4* o = (float4*)&out[(size_t)nn * 64 + kb];
            o[0] = make_float4(r[0], r[1], r[2], r[3]);
            o[1] = make_float4(r[4], r[5], r[6], r[7]);
        }
    }
}

// ---------------- launch ----------------
extern "C" void kernel_launch(void* const* d_in, const int* in_sizes, int n_in,
                              void* d_out, int out_size) {
    const float* emb     = (const float*)d_in[0];
    const float* W       = (const float*)d_in[1];
    const float* att_src = (const float*)d_in[2];
    const float* att_dst = (const float*)d_in[3];
    const float* bias    = (const float*)d_in[4];
    const float* W1      = (const float*)d_in[5];
    const float* b1      = (const float*)d_in[6];
    const float* W2      = (const float*)d_in[7];
    const float* b2      = (const float*)d_in[8];
    const int*   edges   = (const int*)d_in[9];
    const int*   nodes   = (const int*)d_in[10];
    float*       out     = (float*)d_out;

    const int SMEM_BYTES = (4096 + 128 * PAD) * 4;   // 51200
    cudaFuncSetAttribute(gemm_s_kernel, cudaFuncAttributeMaxDynamicSharedMemorySize, SMEM_BYTES);
    cudaFuncSetAttribute(final_acc,     cudaFuncAttributeMaxDynamicSharedMemorySize, SMEM_BYTES);
    cudaFuncSetAttribute(final_finish,  cudaFuncAttributeMaxDynamicSharedMemorySize, SMEM_BYTES);

    const size_t tot4 = (size_t)N_REL * N_NODES * HID / 4;
    zero_kernel<<<(unsigned)((tot4 + 255) / 256), 256>>>();

    const int nb = (N_NODES + 127) / 128;   // 235
    for (int c = 0; c < 5; ++c) {
        int r0 = c * 8;
        int nr = (c == 4) ? 6 : 8;
        dim3 g1(nb, nr);
        gemm_s_kernel<<<g1, 256, SMEM_BYTES>>>(emb, W, att_src, att_dst, r0);
    }

    const int sblocks = (E_TOT * 8 + 255) / 256;
    for (int r = 0; r < N_REL; r += 2) {
        dim3 gs(sblocks, 2);
        scatter_kernel<<<gs, 256>>>(edges, r);
    }

    dim3 gacc(nb, N_CHUNK);
    final_acc<<<gacc, 256, SMEM_BYTES>>>(emb, bias, W1, nodes);
    final_finish<<<nb, 256, SMEM_BYTES>>>(b1, W2, b2, out);
}

// round 7
// speedup vs baseline: 2.2131x; 1.1937x over previous
#include <cuda_runtime.h>
#include <math.h>

#define N_NODES 30000
#define N_REL   38
#define N_EDGE  200000
#define HID     64
#define PAD     68                    // smem row pitch (floats): 16B-aligned, conflict-free
#define N_CHUNK 5                     // final_acc seg chunks (8,8,8,8,7)

// packed fp32x2 helpers (Blackwell FFMA2 — ptxas never auto-generates these)
#define FMA2(acc, a, b) asm("fma.rn.f32x2 %0, %1, %2, %0;" : "+l"(acc) : "l"(a), "l"(b))
#define PACK2(out, x)   asm("mov.b64 %0, {%1, %1};" : "=l"(out) : "f"(x))
#define UNPK2(lo, hi, in) asm("mov.b64 {%0, %1}, %2;" : "=f"(lo), "=f"(hi) : "l"(in))

// ---------------- scratch ----------------
__device__ float g_H  [(size_t)N_REL * N_NODES * HID];
__device__ float g_OUT[(size_t)N_REL * N_NODES * HID];   // init by gemm epilogue: w_self*h
__device__ float g_Ssrc[N_REL * N_NODES];
__device__ float g_Sdst[N_REL * N_NODES];
__device__ float g_DEN [N_REL * N_NODES];                // init by gemm epilogue: w_self
__device__ float g_PREP[N_CHUNK][(size_t)N_NODES * HID]; // pre-tanh partial sums

__device__ __forceinline__ float lrelu(float x) { return x > 0.f ? x : 0.2f * x; }

// 256-row x 64-col tile mainloop: thread = 8 rows (r0+32m) x 8 cols (kb..kb+7).
// sA pitch PAD, sB 64x64. 1.0 B/FMA smem traffic (balanced for L1 vs FFMA2).
__device__ __forceinline__ void mma_rows8(
    const float* sA, const float* sB, int r0, int kb, unsigned long long accp[8][4])
{
    for (int j4 = 0; j4 < 16; ++j4) {
        float4 E[8];
#pragma unroll
        for (int m = 0; m < 8; m++)
            E[m] = *(const float4*)&sA[(r0 + m * 32) * PAD + j4 * 4];
#pragma unroll
        for (int jj = 0; jj < 4; ++jj) {
            const ulonglong2* wv = (const ulonglong2*)&sB[(j4 * 4 + jj) * 64 + kb];
            ulonglong2 wA = wv[0], wB = wv[1];
#pragma unroll
            for (int m = 0; m < 8; m++) {
                unsigned long long ep;
                PACK2(ep, ((const float*)&E[m])[jj]);
                FMA2(accp[m][0], ep, wA.x); FMA2(accp[m][1], ep, wA.y);
                FMA2(accp[m][2], ep, wB.x); FMA2(accp[m][3], ep, wB.y);
            }
        }
    }
}

// ---------------- per-relation GEMM + attention scores + fused self-loop ----------------
__global__ __launch_bounds__(256) void gemm_s_kernel(
    const float* __restrict__ emb, const float* __restrict__ W,
    const float* __restrict__ att_src, const float* __restrict__ att_dst, int rel0)
{
    extern __shared__ float smem[];
    float* sW = smem;            // 64*64
    float* sE = smem + 4096;     // 256*PAD

    const int rel = rel0 + blockIdx.y;
    const int n0  = blockIdx.x * 256;
    const int tid = threadIdx.x;

    const float* Wr = W + rel * 4096;
    for (int i = tid; i < 1024; i += 256)
        ((float4*)sW)[i] = ((const float4*)Wr)[i];
    for (int i = tid; i < 4096; i += 256) {
        int row = i >> 4, k = (i & 15) * 4;
        int n = n0 + row;
        float4 v = make_float4(0.f, 0.f, 0.f, 0.f);
        if (n < N_NODES) v = *(const float4*)&emb[(size_t)n * 64 + k];
        *(float4*)&sE[row * PAD + k] = v;
    }

    const int kb = (tid & 7) * 8;
    float as[8], ad[8];
#pragma unroll
    for (int q = 0; q < 8; q++) {
        as[q] = att_src[rel * 64 + kb + q];
        ad[q] = att_dst[rel * 64 + kb + q];
    }
    __syncthreads();

    const int r0 = tid >> 3;     // 0..31 ; rows r0 + 32m, m=0..7
    unsigned long long accp[8][4];
#pragma unroll
    for (int m = 0; m < 8; m++)
#pragma unroll
        for (int p = 0; p < 4; p++) accp[m][p] = 0ULL;

    mma_rows8(sE, sW, r0, kb, accp);

    // scores: per-row dot with att vectors, 8-lane butterfly (all lanes get full sum)
    float ps[8], pd[8];
#pragma unroll
    for (int m = 0; m < 8; m++) {
        float a = 0.f, b = 0.f;
#pragma unroll
        for (int p = 0; p < 4; p++) {
            float lo, hi;
            UNPK2(lo, hi, accp[m][p]);
            a += lo * as[p * 2] + hi * as[p * 2 + 1];
            b += lo * ad[p * 2] + hi * ad[p * 2 + 1];
        }
        ps[m] = a; pd[m] = b;
    }
#pragma unroll
    for (int off = 1; off < 8; off <<= 1) {
#pragma unroll
        for (int m = 0; m < 8; m++) {
            ps[m] += __shfl_xor_sync(0xffffffffu, ps[m], off);
            pd[m] += __shfl_xor_sync(0xffffffffu, pd[m], off);
        }
    }

#pragma unroll
    for (int m = 0; m < 8; m++) {
        int n = n0 + r0 + m * 32;
        if (n < N_NODES) {
            float wself = __expf(lrelu(ps[m] + pd[m]));
            float r[8];
#pragma unroll
            for (int p = 0; p < 4; p++) {
                float lo, hi;
                UNPK2(lo, hi, accp[m][p]);
                r[p * 2] = lo; r[p * 2 + 1] = hi;
            }
            size_t base = ((size_t)rel * N_NODES + n) * 64 + kb;
            float4* hp = (float4*)&g_H[base];
            hp[0] = make_float4(r[0], r[1], r[2], r[3]);
            hp[1] = make_float4(r[4], r[5], r[6], r[7]);
            float4* op = (float4*)&g_OUT[base];
            op[0] = make_float4(wself*r[0], wself*r[1], wself*r[2], wself*r[3]);
            op[1] = make_float4(wself*r[4], wself*r[5], wself*r[6], wself*r[7]);
            if ((tid & 7) == 0) {
                g_Ssrc[rel * N_NODES + n] = ps[m];
                g_Sdst[rel * N_NODES + n] = pd[m];
                g_DEN [rel * N_NODES + n] = wself;
            }
        }
    }
}

// ---------------- scatter (real edges only): OUT[dst] += w*H[src], DEN[dst] += w ----------------
// 8 lanes/edge, all lanes compute (broadcast loads), lane sub==0 does DEN atomic.
// Grid exact: N_EDGE*8 = 1,600,000 = 6250*256.
__global__ __launch_bounds__(256) void scatter_kernel(const int* __restrict__ edges) {
    const int rel  = blockIdx.y;
    const int t    = blockIdx.x * 256 + threadIdx.x;
    const int edge = t >> 3;
    const int sub  = threadIdx.x & 7;

    const int* eb = edges + (size_t)rel * 2 * N_EDGE;
    const int s = __ldg(&eb[edge]);
    const int d = __ldg(&eb[N_EDGE + edge]);
    float e = lrelu(__ldg(&g_Ssrc[rel * N_NODES + s]) + __ldg(&g_Sdst[rel * N_NODES + d]));
    float w = __expf(e);
    if (sub == 0) atomicAdd(&g_DEN[rel * N_NODES + d], w);

    const size_t hb = ((size_t)rel * N_NODES + s) * 64 + sub * 4;
    const size_t ob = ((size_t)rel * N_NODES + d) * 64 + sub * 4;
    float4 h0 = *(const float4*)&g_H[hb];
    float4 h1 = *(const float4*)&g_H[hb + 32];
    float* o0 = &g_OUT[ob];
    float* o1 = &g_OUT[ob + 32];
    asm volatile("red.global.add.v4.f32 [%0], {%1,%2,%3,%4};"
                 :: "l"(o0), "f"(w * h0.x), "f"(w * h0.y),
                    "f"(w * h0.z), "f"(w * h0.w) : "memory");
    asm volatile("red.global.add.v4.f32 [%0], {%1,%2,%3,%4};"
                 :: "l"(o1), "f"(w * h1.x), "f"(w * h1.y),
                    "f"(w * h1.z), "f"(w * h1.w) : "memory");
}

// ---------------- final_acc: partial pre-tanh sums over an 8-seg chunk ----------------
__global__ __launch_bounds__(256) void final_acc(
    const float* __restrict__ emb, const float* __restrict__ bias,
    const float* __restrict__ W1, const int* __restrict__ nodes)
{
    extern __shared__ float smem[];
    float* sA = smem;                // 256*PAD
    float* sB = smem + 256 * PAD;    // 64*64
    __shared__ float sInv[256];
    __shared__ int   sNd[256];

    const int chunk = blockIdx.y;
    const int seg0  = chunk * 8;
    const int seg1  = (seg0 + 8 < N_REL + 1) ? seg0 + 8 : N_REL + 1;
    const int n0  = blockIdx.x * 256;
    const int tid = threadIdx.x;
    const int r0  = tid >> 3;
    const int kb  = (tid & 7) * 8;

    {
        int nn = n0 + tid;
        sNd[tid] = (nn < N_NODES) ? nodes[nn] : -1;
    }

    unsigned long long accp[8][4];
#pragma unroll
    for (int m = 0; m < 8; m++)
#pragma unroll
        for (int p = 0; p < 4; p++) accp[m][p] = 0ULL;

    for (int seg = seg0; seg < seg1; ++seg) {
        __syncthreads();
        const float* w1c = W1 + (size_t)seg * 4096;
        for (int i = tid; i < 1024; i += 256)
            ((float4*)sB)[i] = ((const float4*)w1c)[i];
        if (seg > 0) {
            int nd = sNd[tid];
            sInv[tid] = (nd >= 0) ? (1.f / g_DEN[(seg - 1) * N_NODES + nd]) : 0.f;
        }
        __syncthreads();

        if (seg == 0) {
            for (int i = tid; i < 4096; i += 256) {
                int row = i >> 4, k = (i & 15) * 4;
                int nd = sNd[row];
                float4 v = make_float4(0.f, 0.f, 0.f, 0.f);
                if (nd >= 0) v = *(const float4*)&emb[(size_t)nd * 64 + k];
                *(float4*)&sA[row * PAD + k] = v;
            }
        } else {
            const int r = seg - 1;
            for (int i = tid; i < 4096; i += 256) {
                int row = i >> 4, k = (i & 15) * 4;
                int nd = sNd[row];
                float4 v = make_float4(0.f, 0.f, 0.f, 0.f);
                if (nd >= 0) {
                    float4 o    = *(const float4*)&g_OUT[((size_t)r * N_NODES + nd) * 64 + k];
                    float4 bvec = *(const float4*)&bias[r * 64 + k];
                    float inv = sInv[row];
                    v.x = o.x * inv + bvec.x;
                    v.y = o.y * inv + bvec.y;
                    v.z = o.z * inv + bvec.z;
                    v.w = o.w * inv + bvec.w;
                }
                *(float4*)&sA[row * PAD + k] = v;
            }
        }
        __syncthreads();

        mma_rows8(sA, sB, r0, kb, accp);
    }

    float* prep = g_PREP[chunk];
#pragma unroll
    for (int m = 0; m < 8; m++) {
        int nn = n0 + r0 + m * 32;
        if (nn < N_NODES) {
            ulonglong2* pp = (ulonglong2*)&prep[(size_t)nn * 64 + kb];
            pp[0] = make_ulonglong2(accp[m][0], accp[m][1]);
            pp[1] = make_ulonglong2(accp[m][2], accp[m][3]);
        }
    }
}

// ---------------- final_finish: sum partials, tanh, @W2 + b2 ----------------
__global__ __launch_bounds__(256) void final_finish(
    const float* __restrict__ b1, const float* __restrict__ W2,
    const float* __restrict__ b2, float* __restrict__ out)
{
    extern __shared__ float smem[];
    float* sA = smem;
    float* sB = smem + 256 * PAD;

    const int n0  = blockIdx.x * 256;
    const int tid = threadIdx.x;
    const int r0  = tid >> 3;
    const int kb  = (tid & 7) * 8;

    for (int i = tid; i < 1024; i += 256)
        ((float4*)sB)[i] = ((const float4*)W2)[i];

    for (int i = tid; i < 4096; i += 256) {
        int row = i >> 4, k = (i & 15) * 4;
        int nn = n0 + row;
        float4 v = make_float4(0.f, 0.f, 0.f, 0.f);
        if (nn < N_NODES) {
            size_t off = (size_t)nn * 64 + k;
#pragma unroll
            for (int c = 0; c < N_CHUNK; ++c) {
                float4 p = *(const float4*)&g_PREP[c][off];
                v.x += p.x; v.y += p.y; v.z += p.z; v.w += p.w;
            }
            float4 bb = *(const float4*)&b1[k];
            v.x = tanhf(v.x + bb.x); v.y = tanhf(v.y + bb.y);
            v.z = tanhf(v.z + bb.z); v.w = tanhf(v.w + bb.w);
        }
        *(float4*)&sA[row * PAD + k] = v;
    }
    __syncthreads();

    unsigned long long accp[8][4];
#pragma unroll
    for (int m = 0; m < 8; m++)
#pragma unroll
        for (int p = 0; p < 4; p++) accp[m][p] = 0ULL;

    mma_rows8(sA, sB, r0, kb, accp);

    float b2v[8];
#pragma unroll
    for (int q = 0; q < 8; q++) b2v[q] = b2[kb + q];
#pragma unroll
    for (int m = 0; m < 8; m++) {
        int nn = n0 + r0 + m * 32;
        if (nn < N_NODES) {
            float r[8];
#pragma unroll
            for (int p = 0; p < 4; p++) {
                float lo, hi;
                UNPK2(lo, hi, accp[m][p]);
                r[p * 2]     = lo + b2v[p * 2];
                r[p * 2 + 1] = hi + b2v[p * 2 + 1];
            }
            float4* o = (float4*)&out[(size_t)nn * 64 + kb];
            o[0] = make_float4(r[0], r[1], r[2], r[3]);
            o[1] = make_float4(r[4], r[5], r[6], r[7]);
        }
    }
}

// ---------------- launch ----------------
extern "C" void kernel_launch(void* const* d_in, const int* in_sizes, int n_in,
                              void* d_out, int out_size) {
    const float* emb     = (const float*)d_in[0];
    const float* W       = (const float*)d_in[1];
    const float* att_src = (const float*)d_in[2];
    const float* att_dst = (const float*)d_in[3];
    const float* bias    = (const float*)d_in[4];
    const float* W1      = (const float*)d_in[5];
    const float* b1      = (const float*)d_in[6];
    const float* W2      = (const float*)d_in[7];
    const float* b2      = (const float*)d_in[8];
    const int*   edges   = (const int*)d_in[9];
    const int*   nodes   = (const int*)d_in[10];
    float*       out     = (float*)d_out;

    const int SMEM_BYTES = (4096 + 256 * PAD) * 4;   // 86016
    cudaFuncSetAttribute(gemm_s_kernel, cudaFuncAttributeMaxDynamicSharedMemorySize, SMEM_BYTES);
    cudaFuncSetAttribute(final_acc,     cudaFuncAttributeMaxDynamicSharedMemorySize, SMEM_BYTES);
    cudaFuncSetAttribute(final_finish,  cudaFuncAttributeMaxDynamicSharedMemorySize, SMEM_BYTES);

    const int nb = (N_NODES + 255) / 256;   // 118
    // launches 0..4: gemm chunks (8,8,8,8,6) — scatter lands at ncu capture index 5
    for (int c = 0; c < 5; ++c) {
        int r0 = c * 8;
        int nr = (c == 4) ? 6 : 8;
        dim3 g1(nb, nr);
        gemm_s_kernel<<<g1, 256, SMEM_BYTES>>>(emb, W, att_src, att_dst, r0);
    }

    // one scatter launch, x-fastest order keeps per-relation L2 locality
    dim3 gs(N_EDGE * 8 / 256, N_REL);   // (6250, 38), exact
    scatter_kernel<<<gs, 256>>>(edges);

    dim3 gacc(nb, N_CHUNK);
    final_acc<<<gacc, 256, SMEM_BYTES>>>(emb, bias, W1, nodes);
    final_finish<<<nb, 256, SMEM_BYTES>>>(b1, W2, b2, out);
}

// round 9
// speedup vs baseline: 3.5051x; 1.5838x over previous
#include <cuda_runtime.h>
#include <cuda_bf16.h>
#include <math.h>
#include <stdint.h>

#define N_NODES 30000
#define N_REL   38
#define N_EDGE  200000
#define HID     64
#define PAD     68     // fp32 stage row stride
#define ASTR    72     // bf16 smem tile row stride (144B: conflict-free frags)
#define N_CHUNK 5

// ---------------- scratch ----------------
__device__ float g_H  [(size_t)N_REL * N_NODES * HID];
__device__ float g_OUT[(size_t)N_REL * N_NODES * HID];
__device__ float g_Ssrc[N_REL * N_NODES];
__device__ float g_Sdst[N_REL * N_NODES];
__device__ float g_DEN [N_REL * N_NODES];
__device__ float g_PREP[N_CHUNK][(size_t)N_NODES * HID];
__device__ __align__(16) __nv_bfloat16 g_EH [(size_t)N_NODES * HID];
__device__ __align__(16) __nv_bfloat16 g_EL [(size_t)N_NODES * HID];
__device__ __align__(16) __nv_bfloat16 g_WH [(size_t)N_REL * 4096];      // W^T  [rel][out][in]
__device__ __align__(16) __nv_bfloat16 g_WL [(size_t)N_REL * 4096];
__device__ __align__(16) __nv_bfloat16 g_W1H[(size_t)(N_REL + 1) * 4096];// W1^T [seg][out][in]
__device__ __align__(16) __nv_bfloat16 g_W1L[(size_t)(N_REL + 1) * 4096];
__device__ __align__(16) __nv_bfloat16 g_W2H[4096];                      // W2^T [out][in]
__device__ __align__(16) __nv_bfloat16 g_W2L[4096];

__device__ __forceinline__ float lrelu(float x) { return x > 0.f ? x : 0.2f * x; }

__device__ __forceinline__ void split1(float x, __nv_bfloat16& h, __nv_bfloat16& l) {
    h = __float2bfloat16(x);
    l = __float2bfloat16(x - __bfloat162float(h));
}
__device__ __forceinline__ uint32_t pk(__nv_bfloat16 a, __nv_bfloat16 b) {
    __nv_bfloat162 v; v.x = a; v.y = b;
    return *(uint32_t*)&v;
}

// ---------------- mma.sync m16n8k16 bf16 (legacy HMMA path, sm_80+) ----------------
__device__ __forceinline__ void mma16816(float* d, const uint32_t* a, uint32_t b0, uint32_t b1) {
    asm volatile(
        "mma.sync.aligned.m16n8k16.row.col.f32.bf16.bf16.f32 "
        "{%0,%1,%2,%3}, {%4,%5,%6,%7}, {%8,%9}, {%0,%1,%2,%3};"
        : "+f"(d[0]), "+f"(d[1]), "+f"(d[2]), "+f"(d[3])
        : "r"(a[0]), "r"(a[1]), "r"(a[2]), "r"(a[3]), "r"(b0), "r"(b1));
}
__device__ __forceinline__ void lda_frag(uint32_t* a, const __nv_bfloat16* T,
                                         int wr, int j0, int g, int t) {
    a[0] = *(const uint32_t*)&T[(wr + g)     * ASTR + j0 + 2 * t];
    a[1] = *(const uint32_t*)&T[(wr + g + 8) * ASTR + j0 + 2 * t];
    a[2] = *(const uint32_t*)&T[(wr + g)     * ASTR + j0 + 2 * t + 8];
    a[3] = *(const uint32_t*)&T[(wr + g + 8) * ASTR + j0 + 2 * t + 8];
}

// warp computes 16x64 tile over K=64, 3-term bf16 split; acc[8][4] persists across calls
__device__ __forceinline__ void warp_mma_3term(
    const __nv_bfloat16* Ah, const __nv_bfloat16* Al,
    const __nv_bfloat16* Bh, const __nv_bfloat16* Bl,
    int wr, int g, int t, float acc[8][4])
{
#pragma unroll
    for (int kc = 0; kc < 4; ++kc) {
        const int j0 = kc * 16;
        uint32_t ah[4], al[4];
        lda_frag(ah, Ah, wr, j0, g, t);
        lda_frag(al, Al, wr, j0, g, t);
#pragma unroll
        for (int nt = 0; nt < 8; ++nt) {
            const int c = nt * 8 + g;
            uint32_t bh0 = *(const uint32_t*)&Bh[c * ASTR + j0 + 2 * t];
            uint32_t bh1 = *(const uint32_t*)&Bh[c * ASTR + j0 + 2 * t + 8];
            uint32_t bl0 = *(const uint32_t*)&Bl[c * ASTR + j0 + 2 * t];
            uint32_t bl1 = *(const uint32_t*)&Bl[c * ASTR + j0 + 2 * t + 8];
            mma16816(acc[nt], ah, bh0, bh1);
            mma16816(acc[nt], al, bh0, bh1);
            mma16816(acc[nt], ah, bl0, bl1);
        }
    }
}

// store warp acc tile -> fp32 stage
__device__ __forceinline__ void acc_to_stage(float* stage, const float acc[8][4],
                                             int wr, int g, int t) {
#pragma unroll
    for (int nt = 0; nt < 8; ++nt) {
        *(float2*)&stage[(wr + g)     * PAD + nt * 8 + 2 * t] = make_float2(acc[nt][0], acc[nt][1]);
        *(float2*)&stage[(wr + g + 8) * PAD + nt * 8 + 2 * t] = make_float2(acc[nt][2], acc[nt][3]);
    }
}

// ---------------- prep kernels ----------------
__global__ void prep_emb(const float* __restrict__ emb) {
    int i = blockIdx.x * 256 + threadIdx.x;
    if (i < N_NODES * HID / 2) {
        float2 v = ((const float2*)emb)[i];
        __nv_bfloat16 h0, l0, h1, l1;
        split1(v.x, h0, l0); split1(v.y, h1, l1);
        ((uint32_t*)g_EH)[i] = pk(h0, h1);
        ((uint32_t*)g_EL)[i] = pk(l0, l1);
    }
}
__global__ void prep_w(const float* __restrict__ W) {
    int i = blockIdx.x * 256 + threadIdx.x;
    if (i < N_REL * 4096) {
        int rel = i >> 12, r = i & 4095, c = r >> 6, j = r & 63;
        float x = W[(rel << 12) + (j << 6) + c];     // W[rel][j][c] -> [rel][c][j]
        split1(x, g_WH[i], g_WL[i]);
    }
}
__global__ void prep_w1(const float* __restrict__ W1) {
    int i = blockIdx.x * 256 + threadIdx.x;
    if (i < (N_REL + 1) * 4096) {
        int seg = i >> 12, r = i & 4095, c = r >> 6, j = r & 63;
        float x = W1[((size_t)seg * 64 + j) * 64 + c];
        split1(x, g_W1H[i], g_W1L[i]);
    }
}
__global__ void prep_w2(const float* __restrict__ W2) {
    int i = blockIdx.x * 256 + threadIdx.x;
    if (i < 4096) {
        int c = i >> 6, j = i & 63;
        split1(W2[(j << 6) + c], g_W2H[i], g_W2L[i]);
    }
}

// ---------------- gemm: H = emb @ W[r] + scores + fused self-loop ----------------
// 256 threads, 128-node tile, grid (235, 38)
__global__ __launch_bounds__(256) void gemm_mma(
    const float* __restrict__ att_src, const float* __restrict__ att_dst)
{
    extern __shared__ char sm[];
    __nv_bfloat16* Ah = (__nv_bfloat16*)sm;        // 128*ASTR
    __nv_bfloat16* Al = Ah + 128 * ASTR;
    __nv_bfloat16* Bh = Al + 128 * ASTR;           // 64*ASTR
    __nv_bfloat16* Bl = Bh + 64 * ASTR;
    float* stage = (float*)sm;                     // reuse after MMA (128*PAD*4 <= 36864)
    __shared__ float sAs[64], sAd[64], sWf[128];

    const int rel = blockIdx.y;
    const int n0  = blockIdx.x * 128;
    const int tid = threadIdx.x;
    const int wid = tid >> 5, lane = tid & 31, g = lane >> 2, t = lane & 3;

    if (tid < 64) { sAs[tid] = att_src[rel * 64 + tid]; sAd[tid] = att_dst[rel * 64 + tid]; }

    for (int i = tid; i < 1024; i += 256) {        // A tiles: 128 rows x 8 x 16B
        int row = i >> 3, c16 = (i & 7) * 16;
        int n = n0 + row;
        uint4 vh = make_uint4(0, 0, 0, 0), vl = vh;
        if (n < N_NODES) {
            vh = *(const uint4*)((const char*)g_EH + (size_t)n * 128 + c16);
            vl = *(const uint4*)((const char*)g_EL + (size_t)n * 128 + c16);
        }
        *(uint4*)((char*)Ah + row * 144 + c16) = vh;
        *(uint4*)((char*)Al + row * 144 + c16) = vl;
    }
    for (int i = tid; i < 512; i += 256) {         // B tiles: 64 rows x 8 x 16B
        int row = i >> 3, c16 = (i & 7) * 16;
        *(uint4*)((char*)Bh + row * 144 + c16) =
            *(const uint4*)((const char*)g_WH + (size_t)rel * 8192 + row * 128 + c16);
        *(uint4*)((char*)Bl + row * 144 + c16) =
            *(const uint4*)((const char*)g_WL + (size_t)rel * 8192 + row * 128 + c16);
    }
    __syncthreads();

    float acc[8][4];
#pragma unroll
    for (int nt = 0; nt < 8; ++nt)
#pragma unroll
        for (int q = 0; q < 4; ++q) acc[nt][q] = 0.f;

    warp_mma_3term(Ah, Al, Bh, Bl, wid * 16, g, t, acc);
    __syncthreads();                               // tiles dead; stage takes over

    acc_to_stage(stage, acc, wid * 16, g, t);
    __syncthreads();

    // scores: 2 threads per row
    {
        const int row = tid >> 1, half = tid & 1;
        float ss = 0.f, sd = 0.f;
#pragma unroll 8
        for (int c = 0; c < 32; ++c) {
            float v = stage[row * PAD + half * 32 + c];
            ss += v * sAs[half * 32 + c];
            sd += v * sAd[half * 32 + c];
        }
        ss += __shfl_xor_sync(0xffffffffu, ss, 1);
        sd += __shfl_xor_sync(0xffffffffu, sd, 1);
        if (half == 0) {
            float wself = __expf(lrelu(ss + sd));
            sWf[row] = wself;
            int n = n0 + row;
            if (n < N_NODES) {
                g_Ssrc[rel * N_NODES + n] = ss;
                g_Sdst[rel * N_NODES + n] = sd;
                g_DEN [rel * N_NODES + n] = wself;
            }
        }
    }
    __syncthreads();

    for (int i = tid; i < 2048; i += 256) {        // coalesced H/OUT
        int row = i >> 4, q = i & 15;
        int nn = n0 + row;
        if (nn < N_NODES) {
            float4 v = *(float4*)&stage[row * PAD + q * 4];
            float ws = sWf[row];
            size_t b = ((size_t)rel * N_NODES + nn) * 64 + q * 4;
            *(float4*)&g_H[b]   = v;
            *(float4*)&g_OUT[b] = make_float4(ws * v.x, ws * v.y, ws * v.z, ws * v.w);
        }
    }
}

// ---------------- scatter (real edges): OUT[dst] += w*H[src], DEN[dst] += w ----------------
__global__ __launch_bounds__(256) void scatter_kernel(const int* __restrict__ edges, int rel0) {
    const int rel  = rel0 + blockIdx.y;
    const int t    = blockIdx.x * 256 + threadIdx.x;
    const int edge = t >> 3;
    const int sub  = threadIdx.x & 7;

    const int* eb = edges + (size_t)rel * 2 * N_EDGE;
    const int s = __ldg(&eb[edge]);
    const int d = __ldg(&eb[N_EDGE + edge]);
    float e = lrelu(__ldg(&g_Ssrc[rel * N_NODES + s]) + __ldg(&g_Sdst[rel * N_NODES + d]));
    float w = __expf(e);
    if (sub == 0) atomicAdd(&g_DEN[rel * N_NODES + d], w);

    const size_t hb = ((size_t)rel * N_NODES + s) * 64 + sub * 4;
    const size_t ob = ((size_t)rel * N_NODES + d) * 64 + sub * 4;
    float4 h0 = *(const float4*)&g_H[hb];
    float4 h1 = *(const float4*)&g_H[hb + 32];
    float* o0 = &g_OUT[ob];
    float* o1 = &g_OUT[ob + 32];
    asm volatile("red.global.add.v4.f32 [%0], {%1,%2,%3,%4};"
                 :: "l"(o0), "f"(w * h0.x), "f"(w * h0.y), "f"(w * h0.z), "f"(w * h0.w) : "memory");
    asm volatile("red.global.add.v4.f32 [%0], {%1,%2,%3,%4};"
                 :: "l"(o1), "f"(w * h1.x), "f"(w * h1.y), "f"(w * h1.z), "f"(w * h1.w) : "memory");
}

// ---------------- final_acc: partial pre-tanh sums over an 8-seg chunk ----------------
__global__ __launch_bounds__(256) void final_acc(
    const float* __restrict__ emb, const float* __restrict__ bias,
    const int* __restrict__ nodes)
{
    extern __shared__ char sm[];
    __nv_bfloat16* Ah = (__nv_bfloat16*)sm;
    __nv_bfloat16* Al = Ah + 128 * ASTR;
    __nv_bfloat16* Bh = Al + 128 * ASTR;
    __nv_bfloat16* Bl = Bh + 64 * ASTR;
    float* stage = (float*)sm;
    __shared__ float sInv[128];
    __shared__ int   sNd[128];

    const int chunk = blockIdx.y;
    const int seg0  = chunk * 8;
    const int seg1  = (seg0 + 8 < N_REL + 1) ? seg0 + 8 : N_REL + 1;
    const int n0  = blockIdx.x * 128;
    const int tid = threadIdx.x;
    const int wid = tid >> 5, lane = tid & 31, g = lane >> 2, t = lane & 3;

    if (tid < 128) {
        int nn = n0 + tid;
        sNd[tid] = (nn < N_NODES) ? nodes[nn] : -1;
    }

    float acc[8][4];
#pragma unroll
    for (int nt = 0; nt < 8; ++nt)
#pragma unroll
        for (int q = 0; q < 4; ++q) acc[nt][q] = 0.f;

    for (int seg = seg0; seg < seg1; ++seg) {
        __syncthreads();                            // prior MMA reads done
        for (int i = tid; i < 512; i += 256) {      // B = W1^T[seg] hi/lo
            int row = i >> 3, c16 = (i & 7) * 16;
            *(uint4*)((char*)Bh + row * 144 + c16) =
                *(const uint4*)((const char*)g_W1H + (size_t)seg * 8192 + row * 128 + c16);
            *(uint4*)((char*)Bl + row * 144 + c16) =
                *(const uint4*)((const char*)g_W1L + (size_t)seg * 8192 + row * 128 + c16);
        }
        if (seg > 0 && tid < 128) {
            int nd = sNd[tid];
            sInv[tid] = (nd >= 0) ? (1.f / g_DEN[(seg - 1) * N_NODES + nd]) : 0.f;
        }
        __syncthreads();

        // A tile: fp32 value -> bf16 hi/lo
        for (int i = tid; i < 2048; i += 256) {
            int row = i >> 4, k4 = (i & 15) * 4;
            int nd = sNd[row];
            float4 v = make_float4(0.f, 0.f, 0.f, 0.f);
            if (nd >= 0) {
                if (seg == 0) {
                    v = *(const float4*)&emb[(size_t)nd * 64 + k4];
                } else {
                    const int r = seg - 1;
                    float4 o    = *(const float4*)&g_OUT[((size_t)r * N_NODES + nd) * 64 + k4];
                    float4 bv   = *(const float4*)&bias[r * 64 + k4];
                    float inv = sInv[row];
                    v.x = o.x * inv + bv.x; v.y = o.y * inv + bv.y;
                    v.z = o.z * inv + bv.z; v.w = o.w * inv + bv.w;
                }
            }
            __nv_bfloat16 h0, l0, h1, l1, h2, l2, h3, l3;
            split1(v.x, h0, l0); split1(v.y, h1, l1);
            split1(v.z, h2, l2); split1(v.w, h3, l3);
            *(uint2*)((char*)Ah + row * 144 + k4 * 2) = make_uint2(pk(h0, h1), pk(h2, h3));
            *(uint2*)((char*)Al + row * 144 + k4 * 2) = make_uint2(pk(l0, l1), pk(l2, l3));
        }
        __syncthreads();

        warp_mma_3term(Ah, Al, Bh, Bl, wid * 16, g, t, acc);
    }
    __syncthreads();

    acc_to_stage(stage, acc, wid * 16, g, t);
    __syncthreads();

    float* prep = g_PREP[chunk];
    for (int i = tid; i < 2048; i += 256) {
        int row = i >> 4, q = i & 15;
        int nn = n0 + row;
        if (nn < N_NODES)
            *(float4*)&prep[(size_t)nn * 64 + q * 4] = *(float4*)&stage[row * PAD + q * 4];
    }
}

// ---------------- final_finish: sum partials, tanh, @W2 + b2 ----------------
__global__ __launch_bounds__(256) void final_finish(
    const float* __restrict__ b1, const float* __restrict__ b2, float* __restrict__ out)
{
    extern __shared__ char sm[];
    __nv_bfloat16* Ah = (__nv_bfloat16*)sm;
    __nv_bfloat16* Al = Ah + 128 * ASTR;
    __nv_bfloat16* Bh = Al + 128 * ASTR;
    __nv_bfloat16* Bl = Bh + 64 * ASTR;
    float* stage = (float*)sm;

    const int n0  = blockIdx.x * 128;
    const int tid = threadIdx.x;
    const int wid = tid >> 5, lane = tid & 31, g = lane >> 2, t = lane & 3;

    for (int i = tid; i < 512; i += 256) {
        int row = i >> 3, c16 = (i & 7) * 16;
        *(uint4*)((char*)Bh + row * 144 + c16) =
            *(const uint4*)((const char*)g_W2H + row * 128 + c16);
        *(uint4*)((char*)Bl + row * 144 + c16) =
            *(const uint4*)((const char*)g_W2L + row * 128 + c16);
    }

    for (int i = tid; i < 2048; i += 256) {
        int row = i >> 4, k4 = (i & 15) * 4;
        int nn = n0 + row;
        float4 v = make_float4(0.f, 0.f, 0.f, 0.f);
        if (nn < N_NODES) {
            size_t off = (size_t)nn * 64 + k4;
#pragma unroll
            for (int c = 0; c < N_CHUNK; ++c) {
                float4 p = *(const float4*)&g_PREP[c][off];
                v.x += p.x; v.y += p.y; v.z += p.z; v.w += p.w;
            }
            float4 bb = *(const float4*)&b1[k4];
            v.x = tanhf(v.x + bb.x); v.y = tanhf(v.y + bb.y);
            v.z = tanhf(v.z + bb.z); v.w = tanhf(v.w + bb.w);
        }
        __nv_bfloat16 h0, l0, h1, l1, h2, l2, h3, l3;
        split1(v.x, h0, l0); split1(v.y, h1, l1);
        split1(v.z, h2, l2); split1(v.w, h3, l3);
        *(uint2*)((char*)Ah + row * 144 + k4 * 2) = make_uint2(pk(h0, h1), pk(h2, h3));
        *(uint2*)((char*)Al + row * 144 + k4 * 2) = make_uint2(pk(l0, l1), pk(l2, l3));
    }
    __syncthreads();

    float acc[8][4];
#pragma unroll
    for (int nt = 0; nt < 8; ++nt)
#pragma unroll
        for (int q = 0; q < 4; ++q) acc[nt][q] = 0.f;

    warp_mma_3term(Ah, Al, Bh, Bl, wid * 16, g, t, acc);
    __syncthreads();

    acc_to_stage(stage, acc, wid * 16, g, t);
    __syncthreads();

    for (int i = tid; i < 2048; i += 256) {
        int row = i >> 4, q = i & 15;
        int nn = n0 + row;
        if (nn < N_NODES) {
            float4 v  = *(float4*)&stage[row * PAD + q * 4];
            float4 bb = *(const float4*)&b2[q * 4];
            *(float4*)&out[(size_t)nn * 64 + q * 4] =
                make_float4(v.x + bb.x, v.y + bb.y, v.z + bb.z, v.w + bb.w);
        }
    }
}

// ---------------- launch ----------------
extern "C" void kernel_launch(void* const* d_in, const int* in_sizes, int n_in,
                              void* d_out, int out_size) {
    const float* emb     = (const float*)d_in[0];
    const float* W       = (const float*)d_in[1];
    const float* att_src = (const float*)d_in[2];
    const float* att_dst = (const float*)d_in[3];
    const float* bias    = (const float*)d_in[4];
    const float* W1      = (const float*)d_in[5];
    const float* b1      = (const float*)d_in[6];
    const float* W2      = (const float*)d_in[7];
    const float* b2      = (const float*)d_in[8];
    const int*   edges   = (const int*)d_in[9];
    const int*   nodes   = (const int*)d_in[10];
    float*       out     = (float*)d_out;

    const int MMA_SMEM = (128 * ASTR + 128 * ASTR + 64 * ASTR + 64 * ASTR) * 2;  // 55296
    cudaFuncSetAttribute(gemm_mma,     cudaFuncAttributeMaxDynamicSharedMemorySize, MMA_SMEM);
    cudaFuncSetAttribute(final_acc,    cudaFuncAttributeMaxDynamicSharedMemorySize, MMA_SMEM);
    cudaFuncSetAttribute(final_finish, cudaFuncAttributeMaxDynamicSharedMemorySize, MMA_SMEM);

    prep_emb<<<(N_NODES * HID / 2 + 255) / 256, 256>>>(emb);
    prep_w  <<<(N_REL * 4096 + 255) / 256, 256>>>(W);
    prep_w1 <<<((N_REL + 1) * 4096 + 255) / 256, 256>>>(W1);
    prep_w2 <<<(4096 + 255) / 256, 256>>>(W2);

    const int nb = (N_NODES + 127) / 128;   // 235
    dim3 gg(nb, N_REL);
    gemm_mma<<<gg, 256, MMA_SMEM>>>(att_src, att_dst);

    dim3 gs(N_EDGE * 8 / 256, 19);
    scatter_kernel<<<gs, 256>>>(edges, 0);
    scatter_kernel<<<gs, 256>>>(edges, 19);

    dim3 gacc(nb, N_CHUNK);
    final_acc<<<gacc, 256, MMA_SMEM>>>(emb, bias, nodes);
    final_finish<<<nb, 256, MMA_SMEM>>>(b1, b2, out);
}